// round 4
// baseline (speedup 1.0000x reference)
#include <cuda_runtime.h>
#include <cuda_bf16.h>
#include <mma.h>
#include <cstdint>
#include <cstddef>

using namespace nvcuda;

// Problem constants
constexpr int Bc = 8, Tc = 512, Vc = 24, Dc = 512, Hc = 8, DHc = 64, DFFc = 2048;
constexpr int BV = Bc * Vc;              // 192
constexpr int MTOK = BV * Tc;            // 98304 tokens

// ---------------- scratch (device globals; allocation-free rule) ----------------
__device__ float g_xn[(size_t)MTOK * Dc];     // LN1 out / attention out (reused)
__device__ float g_q [(size_t)MTOK * Dc];     // Q (head-major) / LN2 out (reused)
__device__ float g_k [(size_t)MTOK * Dc];
__device__ float g_v [(size_t)MTOK * Dc];
__device__ float g_xr[(size_t)MTOK * Dc];     // residual stream after attention
__device__ float g_ff[(size_t)MTOK * DFFc];   // FFN hidden

// ---------------- helpers ----------------
template <typename Frag>
__device__ __forceinline__ void frag_to_tf32(Frag& f) {
#pragma unroll
    for (int i = 0; i < f.num_elements; i++) f.x[i] = wmma::__float_to_tf32(f.x[i]);
}

// ---------------- LayerNorm: one warp per token ----------------
__global__ void ln_kernel(const float* __restrict__ in, const float* __restrict__ g,
                          const float* __restrict__ be, float* __restrict__ out, int trans)
{
    int tid = threadIdx.x, wid = tid >> 5, lane = tid & 31;
    int m = blockIdx.x * 8 + wid;   // token index in (BV, T)
    const float* row;
    if (trans) {
        int bv = m >> 9, t = m & 511;
        int b = bv / Vc, v = bv % Vc;
        row = in + ((size_t)((b * Tc + t) * Vc + v)) * Dc;   // gather from (B,T,V,D)
    } else {
        row = in + (size_t)m * Dc;
    }
    float4 x4[4];
    float sum = 0.f, sq = 0.f;
#pragma unroll
    for (int j = 0; j < 4; j++) {
        x4[j] = reinterpret_cast<const float4*>(row)[lane + 32 * j];
        sum += x4[j].x + x4[j].y + x4[j].z + x4[j].w;
        sq  += x4[j].x * x4[j].x + x4[j].y * x4[j].y + x4[j].z * x4[j].z + x4[j].w * x4[j].w;
    }
#pragma unroll
    for (int o = 16; o > 0; o >>= 1) {
        sum += __shfl_xor_sync(0xffffffffu, sum, o);
        sq  += __shfl_xor_sync(0xffffffffu, sq,  o);
    }
    float mean = sum * (1.f / Dc);
    float var  = sq * (1.f / Dc) - mean * mean;
    float rstd = rsqrtf(var + 1e-5f);
    float* orow = out + (size_t)m * Dc;
#pragma unroll
    for (int j = 0; j < 4; j++) {
        int f4 = lane + 32 * j;
        float4 gv = reinterpret_cast<const float4*>(g)[f4];
        float4 bb = reinterpret_cast<const float4*>(be)[f4];
        float4 o;
        o.x = (x4[j].x - mean) * rstd * gv.x + bb.x;
        o.y = (x4[j].y - mean) * rstd * gv.y + bb.y;
        o.z = (x4[j].z - mean) * rstd * gv.z + bb.z;
        o.w = (x4[j].w - mean) * rstd * gv.w + bb.w;
        reinterpret_cast<float4*>(orow)[f4] = o;
    }
}

// ---------------- tf32 wmma GEMM: C = A[MxK] * B[KxN] (+ fused epilogue) ----------------
// EPI 0: QKV -> out[((bv*H+h)*T+t)*DH+dh] = v + bias
// EPI 1: Oproj -> out[m*D+n] = v + bias + x_src(transposed gather)
// EPI 2: FFN1  -> out[m*N+n] = gelu(v + bias)
// EPI 3: FFN2  -> d_out[((b*T+t)*V+v)*D+n] = v + bias + resid[m*D+n]
constexpr int BM = 128, BN = 128, BKg = 16;
constexpr int ALD = 24, BLD = 136, SLDg = 136;

template <int EPI>
__global__ void gemm_kernel(const float* __restrict__ A, const float* __restrict__ B,
                            int M, int N, int K,
                            const float* __restrict__ bias,
                            const float* __restrict__ aux,
                            float* __restrict__ out)
{
    extern __shared__ float sm[];
    float* As = sm;                  // [128][24]
    float* Bs = sm + BM * ALD;       // [16][136]

    const int tid = threadIdx.x, wid = tid >> 5;
    const int wm = wid & 3, wn = wid >> 2;          // 4x2 warp grid, each warp 32x64
    const int m0 = blockIdx.y * BM, n0 = blockIdx.x * BN;

    wmma::fragment<wmma::accumulator, 16, 16, 8, float> acc[2][4];
#pragma unroll
    for (int i = 0; i < 2; i++)
#pragma unroll
        for (int j = 0; j < 4; j++) wmma::fill_fragment(acc[i][j], 0.0f);

    for (int k0 = 0; k0 < K; k0 += BKg) {
#pragma unroll
        for (int i = 0; i < 2; i++) {               // A tile: 128x16 = 512 float4
            int f = tid * 2 + i;
            int r = f >> 2, c4 = f & 3;
            float4 v = *reinterpret_cast<const float4*>(A + (size_t)(m0 + r) * K + k0 + c4 * 4);
            *reinterpret_cast<float4*>(As + r * ALD + c4 * 4) = v;
        }
#pragma unroll
        for (int i = 0; i < 2; i++) {               // B tile: 16x128 = 512 float4
            int f = tid * 2 + i;
            int r = f >> 5, c4 = f & 31;
            float4 v = *reinterpret_cast<const float4*>(B + (size_t)(k0 + r) * N + n0 + c4 * 4);
            *reinterpret_cast<float4*>(Bs + r * BLD + c4 * 4) = v;
        }
        __syncthreads();
#pragma unroll
        for (int kk = 0; kk < BKg; kk += 8) {
            wmma::fragment<wmma::matrix_a, 16, 16, 8, wmma::precision::tf32, wmma::row_major> af[2];
            wmma::fragment<wmma::matrix_b, 16, 16, 8, wmma::precision::tf32, wmma::row_major> bf[4];
#pragma unroll
            for (int i = 0; i < 2; i++) {
                wmma::load_matrix_sync(af[i], As + (wm * 32 + i * 16) * ALD + kk, ALD);
                frag_to_tf32(af[i]);
            }
#pragma unroll
            for (int j = 0; j < 4; j++) {
                wmma::load_matrix_sync(bf[j], Bs + kk * BLD + wn * 64 + j * 16, BLD);
                frag_to_tf32(bf[j]);
            }
#pragma unroll
            for (int i = 0; i < 2; i++)
#pragma unroll
                for (int j = 0; j < 4; j++)
                    wmma::mma_sync(acc[i][j], af[i], bf[j], acc[i][j]);
        }
        __syncthreads();
    }

    // Stage accumulators to smem, then fused epilogue
    float* St = sm;                   // [128][136]
#pragma unroll
    for (int i = 0; i < 2; i++)
#pragma unroll
        for (int j = 0; j < 4; j++)
            wmma::store_matrix_sync(St + (wm * 32 + i * 16) * SLDg + wn * 64 + j * 16,
                                    acc[i][j], SLDg, wmma::mem_row_major);
    __syncthreads();

    for (int idx = tid; idx < BM * BN; idx += 256) {
        int r = idx >> 7, c = idx & 127;
        float v = St[r * SLDg + c];
        int gm = m0 + r, gn = n0 + c;
        v += bias[gn];
        if (EPI == 0) {
            int bv = gm >> 9, t = gm & 511, h = gn >> 6, dh = gn & 63;
            out[(((size_t)(bv * Hc + h) * Tc + t) << 6) + dh] = v;
        } else if (EPI == 1) {
            int bv = gm >> 9, t = gm & 511, b = bv / Vc, vv = bv % Vc;
            v += aux[((size_t)((b * Tc + t) * Vc + vv) << 9) + gn];
            out[((size_t)gm << 9) + gn] = v;
        } else if (EPI == 2) {
            v = 0.5f * v * (1.0f + erff(v * 0.70710678118654752f));
            out[(size_t)gm * N + gn] = v;
        } else {
            int bv = gm >> 9, t = gm & 511, b = bv / Vc, vv = bv % Vc;
            v += aux[((size_t)gm << 9) + gn];
            out[((size_t)((b * Tc + t) * Vc + vv) << 9) + gn] = v;
        }
    }
}

// ---------------- Attention: one block = (bv, h, 32-query tile) ----------------
constexpr int QB = 32;
constexpr int SLD = 520;   // 512 + 8 pad

__global__ void attn_kernel(const float* __restrict__ Q, const float* __restrict__ K,
                            const float* __restrict__ V, const int* __restrict__ mask,
                            float* __restrict__ out)
{
    extern __shared__ float s[];      // [QB][SLD] scores -> probs
    int tid = threadIdx.x, wid = tid >> 5;
    int q0 = blockIdx.x * QB, h = blockIdx.y, bv = blockIdx.z;
    const float* Qh = Q + (size_t)(bv * Hc + h) * Tc * DHc;
    const float* Kh = K + (size_t)(bv * Hc + h) * Tc * DHc;
    const float* Vh = V + (size_t)(bv * Hc + h) * Tc * DHc;

    // Phase A: S = Q K^T / 8   (64 tiles of 16x16; 2 rows x 32 cols)
    for (int tile = wid; tile < 64; tile += 8) {
        int tm = tile & 1, tn = tile >> 1;
        wmma::fragment<wmma::accumulator, 16, 16, 8, float> acc;
        wmma::fill_fragment(acc, 0.0f);
#pragma unroll
        for (int k = 0; k < DHc; k += 8) {
            wmma::fragment<wmma::matrix_a, 16, 16, 8, wmma::precision::tf32, wmma::row_major> af;
            wmma::fragment<wmma::matrix_b, 16, 16, 8, wmma::precision::tf32, wmma::col_major> bf;
            wmma::load_matrix_sync(af, Qh + (size_t)(q0 + tm * 16) * DHc + k, DHc);
            frag_to_tf32(af);
            wmma::load_matrix_sync(bf, Kh + (size_t)(tn * 16) * DHc + k, DHc);
            frag_to_tf32(bf);
            wmma::mma_sync(acc, af, bf, acc);
        }
#pragma unroll
        for (int e = 0; e < acc.num_elements; e++) acc.x[e] *= 0.125f;   // 1/sqrt(64)
        wmma::store_matrix_sync(s + tm * 16 * SLD + tn * 16, acc, SLD, wmma::mem_row_major);
    }
    __syncthreads();

    // Softmax over each of 32 rows, 8 threads per row
    // NOTE: mask arrives as int32 (harness materializes jax bool as int32).
    {
        int row = tid >> 3, sub = tid & 7;
        float* base = s + row * SLD;
        int b = bv / Vc;
        const int* mrow = mask + (size_t)b * Tc;
        float mx = -INFINITY;
        for (int j = sub; j < Tc; j += 8) if (mrow[j] != 0) mx = fmaxf(mx, base[j]);
        mx = fmaxf(mx, __shfl_xor_sync(0xffffffffu, mx, 1));
        mx = fmaxf(mx, __shfl_xor_sync(0xffffffffu, mx, 2));
        mx = fmaxf(mx, __shfl_xor_sync(0xffffffffu, mx, 4));
        float sum = 0.f;
        for (int j = sub; j < Tc; j += 8) {
            float p = (mrow[j] != 0) ? __expf(base[j] - mx) : 0.f;
            base[j] = p;
            sum += p;
        }
        sum += __shfl_xor_sync(0xffffffffu, sum, 1);
        sum += __shfl_xor_sync(0xffffffffu, sum, 2);
        sum += __shfl_xor_sync(0xffffffffu, sum, 4);
        float inv = 1.f / sum;
        for (int j = sub; j < Tc; j += 8) base[j] *= inv;
    }
    __syncthreads();

    // Phase B: O = P V   (8 tiles of 16x16; one per warp)
    {
        int tm = wid & 1, tn = wid >> 1;
        wmma::fragment<wmma::accumulator, 16, 16, 8, float> acc;
        wmma::fill_fragment(acc, 0.0f);
#pragma unroll 8
        for (int k = 0; k < Tc; k += 8) {
            wmma::fragment<wmma::matrix_a, 16, 16, 8, wmma::precision::tf32, wmma::row_major> af;
            wmma::fragment<wmma::matrix_b, 16, 16, 8, wmma::precision::tf32, wmma::row_major> bf;
            wmma::load_matrix_sync(af, s + tm * 16 * SLD + k, SLD);
            frag_to_tf32(af);
            wmma::load_matrix_sync(bf, Vh + (size_t)k * DHc + tn * 16, DHc);
            frag_to_tf32(bf);
            wmma::mma_sync(acc, af, bf, acc);
        }
        float* optr = out + (size_t)(bv * Tc + q0 + tm * 16) * Dc + h * DHc + tn * 16;
        wmma::store_matrix_sync(optr, acc, Dc, wmma::mem_row_major);
    }
}

// ---------------- launch ----------------
extern "C" void kernel_launch(void* const* d_in, const int* in_sizes, int n_in,
                              void* d_out, int out_size)
{
    const float* x  = (const float*)d_in[0];
    const int* mask = (const int*)d_in[1];          // bool -> int32 in harness
    const float* Wq = (const float*)d_in[2];
    const float* bq = (const float*)d_in[3];
    const float* Wk = (const float*)d_in[4];
    const float* bk = (const float*)d_in[5];
    const float* Wv = (const float*)d_in[6];
    const float* bvb = (const float*)d_in[7];
    const float* Wo = (const float*)d_in[8];
    const float* bo = (const float*)d_in[9];
    const float* W1 = (const float*)d_in[10];
    const float* b1 = (const float*)d_in[11];
    const float* W2 = (const float*)d_in[12];
    const float* b2 = (const float*)d_in[13];
    const float* g1 = (const float*)d_in[14];
    const float* be1 = (const float*)d_in[15];
    const float* g2 = (const float*)d_in[16];
    const float* be2 = (const float*)d_in[17];
    float* out = (float*)d_out;

    float *xn, *q, *k, *v, *xr, *ff;
    cudaGetSymbolAddress((void**)&xn, g_xn);
    cudaGetSymbolAddress((void**)&q,  g_q);
    cudaGetSymbolAddress((void**)&k,  g_k);
    cudaGetSymbolAddress((void**)&v,  g_v);
    cudaGetSymbolAddress((void**)&xr, g_xr);
    cudaGetSymbolAddress((void**)&ff, g_ff);

    const size_t SMG = (size_t)BM * SLDg * sizeof(float);   // 69632 B (staging dominates)
    const size_t SMA = (size_t)QB * SLD * sizeof(float);    // 66560 B
    cudaFuncSetAttribute(gemm_kernel<0>, cudaFuncAttributeMaxDynamicSharedMemorySize, (int)SMG);
    cudaFuncSetAttribute(gemm_kernel<1>, cudaFuncAttributeMaxDynamicSharedMemorySize, (int)SMG);
    cudaFuncSetAttribute(gemm_kernel<2>, cudaFuncAttributeMaxDynamicSharedMemorySize, (int)SMG);
    cudaFuncSetAttribute(gemm_kernel<3>, cudaFuncAttributeMaxDynamicSharedMemorySize, (int)SMG);
    cudaFuncSetAttribute(attn_kernel,    cudaFuncAttributeMaxDynamicSharedMemorySize, (int)SMA);

    dim3 g512(Dc / BN, MTOK / BM);     // (4, 768)
    dim3 gff(DFFc / BN, MTOK / BM);    // (16, 768)

    // 1. LN1 (gather-transpose from x)
    ln_kernel<<<MTOK / 8, 256>>>(x, g1, be1, xn, 1);
    // 2. QKV projections -> head-major (BV, H, T, DH)
    gemm_kernel<0><<<g512, 256, SMG>>>(xn, Wq, MTOK, Dc, Dc, bq,  nullptr, q);
    gemm_kernel<0><<<g512, 256, SMG>>>(xn, Wk, MTOK, Dc, Dc, bk,  nullptr, k);
    gemm_kernel<0><<<g512, 256, SMG>>>(xn, Wv, MTOK, Dc, Dc, bvb, nullptr, v);
    // 3. Attention -> xn (reused)
    attn_kernel<<<dim3(Tc / QB, Hc, BV), 256, SMA>>>(q, k, v, mask, xn);
    // 4. O-projection + residual (x gathered) -> xr
    gemm_kernel<1><<<g512, 256, SMG>>>(xn, Wo, MTOK, Dc, Dc, bo, x, xr);
    // 5. LN2 -> q (reused as h)
    ln_kernel<<<MTOK / 8, 256>>>(xr, g2, be2, q, 0);
    // 6. FFN1 + bias + exact gelu -> ff
    gemm_kernel<2><<<gff, 256, SMG>>>(q, W1, MTOK, DFFc, Dc, b1, nullptr, ff);
    // 7. FFN2 + bias + residual + scatter-transpose -> d_out
    gemm_kernel<3><<<g512, 256, SMG>>>(ff, W2, MTOK, Dc, DFFc, b2, xr, out);
}

// round 6
// speedup vs baseline: 1.2839x; 1.2839x over previous
#include <cuda_runtime.h>
#include <cuda_bf16.h>
#include <mma.h>
#include <cstdint>
#include <cstddef>

using namespace nvcuda;

// Problem constants
constexpr int Bc = 8, Tc = 512, Vc = 24, Dc = 512, Hc = 8, DHc = 64, DFFc = 2048;
constexpr int BV = Bc * Vc;              // 192
constexpr int MTOK = BV * Tc;            // 98304 tokens

// ---------------- scratch (device globals; allocation-free rule) ----------------
__device__ float g_xn[(size_t)MTOK * Dc];     // LN1 out / attention out (reused)
__device__ float g_q [(size_t)MTOK * Dc];     // Q (head-major) / LN2 out (reused)
__device__ float g_k [(size_t)MTOK * Dc];
__device__ float g_v [(size_t)MTOK * Dc];
__device__ float g_xr[(size_t)MTOK * Dc];     // residual stream after attention
__device__ float g_ff[(size_t)MTOK * DFFc];   // FFN hidden

// ---------------- helpers ----------------
template <typename Frag>
__device__ __forceinline__ void frag_to_tf32(Frag& f) {
#pragma unroll
    for (int i = 0; i < f.num_elements; i++) f.x[i] = wmma::__float_to_tf32(f.x[i]);
}

__device__ __forceinline__ void cp_async16(void* smem, const void* g) {
    uint32_t s = (uint32_t)__cvta_generic_to_shared(smem);
    asm volatile("cp.async.cg.shared.global [%0], [%1], 16;\n" :: "r"(s), "l"(g));
}
__device__ __forceinline__ void cp_commit() { asm volatile("cp.async.commit_group;\n"); }
template <int N>
__device__ __forceinline__ void cp_wait() { asm volatile("cp.async.wait_group %0;\n" :: "n"(N)); }

// ---------------- LayerNorm: one warp per token ----------------
__global__ void ln_kernel(const float* __restrict__ in, const float* __restrict__ g,
                          const float* __restrict__ be, float* __restrict__ out, int trans)
{
    int tid = threadIdx.x, wid = tid >> 5, lane = tid & 31;
    int m = blockIdx.x * 8 + wid;   // token index in (BV, T)
    const float* row;
    if (trans) {
        int bv = m >> 9, t = m & 511;
        int b = bv / Vc, v = bv % Vc;
        row = in + ((size_t)((b * Tc + t) * Vc + v)) * Dc;   // gather from (B,T,V,D)
    } else {
        row = in + (size_t)m * Dc;
    }
    float4 x4[4];
    float sum = 0.f, sq = 0.f;
#pragma unroll
    for (int j = 0; j < 4; j++) {
        x4[j] = reinterpret_cast<const float4*>(row)[lane + 32 * j];
        sum += x4[j].x + x4[j].y + x4[j].z + x4[j].w;
        sq  += x4[j].x * x4[j].x + x4[j].y * x4[j].y + x4[j].z * x4[j].z + x4[j].w * x4[j].w;
    }
#pragma unroll
    for (int o = 16; o > 0; o >>= 1) {
        sum += __shfl_xor_sync(0xffffffffu, sum, o);
        sq  += __shfl_xor_sync(0xffffffffu, sq,  o);
    }
    float mean = sum * (1.f / Dc);
    float var  = sq * (1.f / Dc) - mean * mean;
    float rstd = rsqrtf(var + 1e-5f);
    float* orow = out + (size_t)m * Dc;
#pragma unroll
    for (int j = 0; j < 4; j++) {
        int f4 = lane + 32 * j;
        float4 gv = reinterpret_cast<const float4*>(g)[f4];
        float4 bb = reinterpret_cast<const float4*>(be)[f4];
        float4 o;
        o.x = (x4[j].x - mean) * rstd * gv.x + bb.x;
        o.y = (x4[j].y - mean) * rstd * gv.y + bb.y;
        o.z = (x4[j].z - mean) * rstd * gv.z + bb.z;
        o.w = (x4[j].w - mean) * rstd * gv.w + bb.w;
        reinterpret_cast<float4*>(orow)[f4] = o;
    }
}

// ---------------- tf32 wmma GEMM, cp.async double-buffered ----------------
// C = A[MxK] * B[KxN] (+ fused epilogue)
// EPI 0: QKV -> out[((bv*H+h)*T+t)*DH+dh] = v + bias
// EPI 1: Oproj -> out[m*D+n] = v + bias + x_src(transposed gather)
// EPI 2: FFN1  -> out[m*N+n] = gelu(v + bias)
// EPI 3: FFN2  -> d_out[((b*T+t)*V+v)*D+n] = v + bias + resid[m*D+n]
constexpr int BM = 128, BN = 128, BKg = 32;
constexpr int ALD = 36, BLD = 136, SLDg = 136;
constexpr int ASTG = BM * ALD;           // 4608 floats per A stage
constexpr int BSTG = BKg * BLD;          // 4352 floats per B stage
constexpr size_t SMG = (size_t)(2 * (ASTG + BSTG)) * sizeof(float);   // 71680 B

template <int EPI>
__global__ void __launch_bounds__(256, 2)
gemm_kernel(const float* __restrict__ A, const float* __restrict__ B,
            int M, int N, int K,
            const float* __restrict__ bias,
            const float* __restrict__ aux,
            float* __restrict__ out)
{
    extern __shared__ float sm[];
    // layout: As0, As1, Bs0, Bs1
    const int tid = threadIdx.x, wid = tid >> 5;
    const int wm = wid & 3, wn = wid >> 2;          // 4x2 warp grid, warp tile 32x64
    const int m0 = blockIdx.y * BM, n0 = blockIdx.x * BN;

    wmma::fragment<wmma::accumulator, 16, 16, 8, float> acc[2][4];
#pragma unroll
    for (int i = 0; i < 2; i++)
#pragma unroll
        for (int j = 0; j < 4; j++) wmma::fill_fragment(acc[i][j], 0.0f);

    // stage loader: A tile 128x32 (1024 float4), B tile 32x128 (1024 float4)
    auto load_stage = [&](int k0, int buf) {
        float* As = sm + buf * ASTG;
        float* Bs = sm + 2 * ASTG + buf * BSTG;
#pragma unroll
        for (int i = 0; i < 4; i++) {
            int f = tid + 256 * i;
            int r = f >> 3, c4 = f & 7;
            cp_async16(As + r * ALD + c4 * 4, A + (size_t)(m0 + r) * K + k0 + c4 * 4);
        }
#pragma unroll
        for (int i = 0; i < 4; i++) {
            int f = tid + 256 * i;
            int r = f >> 5, c4 = f & 31;
            cp_async16(Bs + r * BLD + c4 * 4, B + (size_t)(k0 + r) * N + n0 + c4 * 4);
        }
    };

    const int nst = K / BKg;
    load_stage(0, 0);
    cp_commit();

    for (int s = 0; s < nst; s++) {
        if (s + 1 < nst) {
            load_stage((s + 1) * BKg, (s + 1) & 1);
            cp_commit();
            cp_wait<1>();          // stage s complete, stage s+1 may be in flight
        } else {
            cp_wait<0>();
        }
        __syncthreads();

        const float* As = sm + (s & 1) * ASTG;
        const float* Bs = sm + 2 * ASTG + (s & 1) * BSTG;
#pragma unroll
        for (int kk = 0; kk < BKg; kk += 8) {
            wmma::fragment<wmma::matrix_a, 16, 16, 8, wmma::precision::tf32, wmma::row_major> af[2];
            wmma::fragment<wmma::matrix_b, 16, 16, 8, wmma::precision::tf32, wmma::row_major> bf[4];
#pragma unroll
            for (int i = 0; i < 2; i++) {
                wmma::load_matrix_sync(af[i], As + (wm * 32 + i * 16) * ALD + kk, ALD);
                frag_to_tf32(af[i]);
            }
#pragma unroll
            for (int j = 0; j < 4; j++) {
                wmma::load_matrix_sync(bf[j], Bs + kk * BLD + wn * 64 + j * 16, BLD);
                frag_to_tf32(bf[j]);
            }
#pragma unroll
            for (int i = 0; i < 2; i++)
#pragma unroll
                for (int j = 0; j < 4; j++)
                    wmma::mma_sync(acc[i][j], af[i], bf[j], acc[i][j]);
        }
        __syncthreads();   // protect smem buffer reuse (overwritten at s+2)
    }

    // Stage accumulators to smem (reuse pipeline smem), then fused epilogue
    float* St = sm;                   // [128][136] = 69632 B <= SMG
#pragma unroll
    for (int i = 0; i < 2; i++)
#pragma unroll
        for (int j = 0; j < 4; j++)
            wmma::store_matrix_sync(St + (wm * 32 + i * 16) * SLDg + wn * 64 + j * 16,
                                    acc[i][j], SLDg, wmma::mem_row_major);
    __syncthreads();

    for (int idx = tid; idx < BM * BN; idx += 256) {
        int r = idx >> 7, c = idx & 127;
        float v = St[r * SLDg + c];
        int gm = m0 + r, gn = n0 + c;
        v += bias[gn];
        if (EPI == 0) {
            int bv = gm >> 9, t = gm & 511, h = gn >> 6, dh = gn & 63;
            out[(((size_t)(bv * Hc + h) * Tc + t) << 6) + dh] = v;
        } else if (EPI == 1) {
            int bv = gm >> 9, t = gm & 511, b = bv / Vc, vv = bv % Vc;
            v += aux[((size_t)((b * Tc + t) * Vc + vv) << 9) + gn];
            out[((size_t)gm << 9) + gn] = v;
        } else if (EPI == 2) {
            v = 0.5f * v * (1.0f + erff(v * 0.70710678118654752f));
            out[(size_t)gm * N + gn] = v;
        } else {
            int bv = gm >> 9, t = gm & 511, b = bv / Vc, vv = bv % Vc;
            v += aux[((size_t)gm << 9) + gn];
            out[((size_t)((b * Tc + t) * Vc + vv) << 9) + gn] = v;
        }
    }
}

// ---------------- Attention: one block = (bv, h, 32-query tile) ----------------
constexpr int QB = 32;
constexpr int SLD = 520;   // 512 + 8 pad

__global__ void attn_kernel(const float* __restrict__ Q, const float* __restrict__ K,
                            const float* __restrict__ V, const int* __restrict__ mask,
                            float* __restrict__ out)
{
    extern __shared__ float s[];      // [QB][SLD] scores -> probs
    int tid = threadIdx.x, wid = tid >> 5;
    int q0 = blockIdx.x * QB, h = blockIdx.y, bv = blockIdx.z;
    const float* Qh = Q + (size_t)(bv * Hc + h) * Tc * DHc;
    const float* Kh = K + (size_t)(bv * Hc + h) * Tc * DHc;
    const float* Vh = V + (size_t)(bv * Hc + h) * Tc * DHc;

    // Phase A: S = Q K^T / 8   (64 tiles of 16x16; 2 rows x 32 cols)
    for (int tile = wid; tile < 64; tile += 8) {
        int tm = tile & 1, tn = tile >> 1;
        wmma::fragment<wmma::accumulator, 16, 16, 8, float> acc;
        wmma::fill_fragment(acc, 0.0f);
#pragma unroll
        for (int k = 0; k < DHc; k += 8) {
            wmma::fragment<wmma::matrix_a, 16, 16, 8, wmma::precision::tf32, wmma::row_major> af;
            wmma::fragment<wmma::matrix_b, 16, 16, 8, wmma::precision::tf32, wmma::col_major> bf;
            wmma::load_matrix_sync(af, Qh + (size_t)(q0 + tm * 16) * DHc + k, DHc);
            frag_to_tf32(af);
            wmma::load_matrix_sync(bf, Kh + (size_t)(tn * 16) * DHc + k, DHc);
            frag_to_tf32(bf);
            wmma::mma_sync(acc, af, bf, acc);
        }
#pragma unroll
        for (int e = 0; e < acc.num_elements; e++) acc.x[e] *= 0.125f;   // 1/sqrt(64)
        wmma::store_matrix_sync(s + tm * 16 * SLD + tn * 16, acc, SLD, wmma::mem_row_major);
    }
    __syncthreads();

    // Softmax over each of 32 rows, 8 threads per row (mask is int32)
    {
        int row = tid >> 3, sub = tid & 7;
        float* base = s + row * SLD;
        int b = bv / Vc;
        const int* mrow = mask + (size_t)b * Tc;
        float mx = -INFINITY;
        for (int j = sub; j < Tc; j += 8) if (mrow[j] != 0) mx = fmaxf(mx, base[j]);
        mx = fmaxf(mx, __shfl_xor_sync(0xffffffffu, mx, 1));
        mx = fmaxf(mx, __shfl_xor_sync(0xffffffffu, mx, 2));
        mx = fmaxf(mx, __shfl_xor_sync(0xffffffffu, mx, 4));
        float sum = 0.f;
        for (int j = sub; j < Tc; j += 8) {
            float p = (mrow[j] != 0) ? __expf(base[j] - mx) : 0.f;
            base[j] = p;
            sum += p;
        }
        sum += __shfl_xor_sync(0xffffffffu, sum, 1);
        sum += __shfl_xor_sync(0xffffffffu, sum, 2);
        sum += __shfl_xor_sync(0xffffffffu, sum, 4);
        float inv = 1.f / sum;
        for (int j = sub; j < Tc; j += 8) base[j] *= inv;
    }
    __syncthreads();

    // Phase B: O = P V   (8 tiles of 16x16; one per warp)
    {
        int tm = wid & 1, tn = wid >> 1;
        wmma::fragment<wmma::accumulator, 16, 16, 8, float> acc;
        wmma::fill_fragment(acc, 0.0f);
#pragma unroll 8
        for (int k = 0; k < Tc; k += 8) {
            wmma::fragment<wmma::matrix_a, 16, 16, 8, wmma::precision::tf32, wmma::row_major> af;
            wmma::fragment<wmma::matrix_b, 16, 16, 8, wmma::precision::tf32, wmma::row_major> bf;
            wmma::load_matrix_sync(af, s + tm * 16 * SLD + k, SLD);
            frag_to_tf32(af);
            wmma::load_matrix_sync(bf, Vh + (size_t)k * DHc + tn * 16, DHc);
            frag_to_tf32(bf);
            wmma::mma_sync(acc, af, bf, acc);
        }
        float* optr = out + (size_t)(bv * Tc + q0 + tm * 16) * Dc + h * DHc + tn * 16;
        wmma::store_matrix_sync(optr, acc, Dc, wmma::mem_row_major);
    }
}

// ---------------- launch ----------------
extern "C" void kernel_launch(void* const* d_in, const int* in_sizes, int n_in,
                              void* d_out, int out_size)
{
    const float* x  = (const float*)d_in[0];
    const int* mask = (const int*)d_in[1];          // bool -> int32 in harness
    const float* Wq = (const float*)d_in[2];
    const float* bq = (const float*)d_in[3];
    const float* Wk = (const float*)d_in[4];
    const float* bk = (const float*)d_in[5];
    const float* Wv = (const float*)d_in[6];
    const float* bvb = (const float*)d_in[7];
    const float* Wo = (const float*)d_in[8];
    const float* bo = (const float*)d_in[9];
    const float* W1 = (const float*)d_in[10];
    const float* b1 = (const float*)d_in[11];
    const float* W2 = (const float*)d_in[12];
    const float* b2 = (const float*)d_in[13];
    const float* g1 = (const float*)d_in[14];
    const float* be1 = (const float*)d_in[15];
    const float* g2 = (const float*)d_in[16];
    const float* be2 = (const float*)d_in[17];
    float* out = (float*)d_out;

    float *xn, *q, *k, *v, *xr, *ff;
    cudaGetSymbolAddress((void**)&xn, g_xn);
    cudaGetSymbolAddress((void**)&q,  g_q);
    cudaGetSymbolAddress((void**)&k,  g_k);
    cudaGetSymbolAddress((void**)&v,  g_v);
    cudaGetSymbolAddress((void**)&xr, g_xr);
    cudaGetSymbolAddress((void**)&ff, g_ff);

    const size_t SMA = (size_t)QB * SLD * sizeof(float);    // 66560 B
    cudaFuncSetAttribute(gemm_kernel<0>, cudaFuncAttributeMaxDynamicSharedMemorySize, (int)SMG);
    cudaFuncSetAttribute(gemm_kernel<1>, cudaFuncAttributeMaxDynamicSharedMemorySize, (int)SMG);
    cudaFuncSetAttribute(gemm_kernel<2>, cudaFuncAttributeMaxDynamicSharedMemorySize, (int)SMG);
    cudaFuncSetAttribute(gemm_kernel<3>, cudaFuncAttributeMaxDynamicSharedMemorySize, (int)SMG);
    cudaFuncSetAttribute(attn_kernel,    cudaFuncAttributeMaxDynamicSharedMemorySize, (int)SMA);

    dim3 g512(Dc / BN, MTOK / BM);     // (4, 768)
    dim3 gff(DFFc / BN, MTOK / BM);    // (16, 768)

    // 1. LN1 (gather-transpose from x)
    ln_kernel<<<MTOK / 8, 256>>>(x, g1, be1, xn, 1);
    // 2. QKV projections -> head-major (BV, H, T, DH)
    gemm_kernel<0><<<g512, 256, SMG>>>(xn, Wq, MTOK, Dc, Dc, bq,  nullptr, q);
    gemm_kernel<0><<<g512, 256, SMG>>>(xn, Wk, MTOK, Dc, Dc, bk,  nullptr, k);
    gemm_kernel<0><<<g512, 256, SMG>>>(xn, Wv, MTOK, Dc, Dc, bvb, nullptr, v);
    // 3. Attention -> xn (reused)
    attn_kernel<<<dim3(Tc / QB, Hc, BV), 256, SMA>>>(q, k, v, mask, xn);
    // 4. O-projection + residual (x gathered) -> xr
    gemm_kernel<1><<<g512, 256, SMG>>>(xn, Wo, MTOK, Dc, Dc, bo, x, xr);
    // 5. LN2 -> q (reused as h)
    ln_kernel<<<MTOK / 8, 256>>>(xr, g2, be2, q, 0);
    // 6. FFN1 + bias + exact gelu -> ff
    gemm_kernel<2><<<gff, 256, SMG>>>(q, W1, MTOK, DFFc, Dc, b1, nullptr, ff);
    // 7. FFN2 + bias + residual + scatter-transpose -> d_out
    gemm_kernel<3><<<g512, 256, SMG>>>(ff, W2, MTOK, Dc, DFFc, b2, xr, out);
}

// round 7
// speedup vs baseline: 1.6120x; 1.2556x over previous
#include <cuda_runtime.h>
#include <cuda_bf16.h>
#include <mma.h>
#include <cstdint>
#include <cstddef>

using namespace nvcuda;

// Problem constants
constexpr int Bc = 8, Tc = 512, Vc = 24, Dc = 512, Hc = 8, DHc = 64, DFFc = 2048;
constexpr int BV = Bc * Vc;              // 192
constexpr int MTOK = BV * Tc;            // 98304 tokens

// ---------------- scratch (device globals; allocation-free rule) ----------------
__device__ float g_xn[(size_t)MTOK * Dc];     // LN1 out / attention out (reused)
__device__ float g_q [(size_t)MTOK * Dc];     // Q (head-major) / LN2 out (reused)
__device__ float g_k [(size_t)MTOK * Dc];
__device__ float g_v [(size_t)MTOK * Dc];
__device__ float g_xr[(size_t)MTOK * Dc];     // residual stream after attention
__device__ float g_ff[(size_t)MTOK * DFFc];   // FFN hidden
// tf32-prerounded weights
__device__ float g_wq[Dc * Dc];
__device__ float g_wk[Dc * Dc];
__device__ float g_wv[Dc * Dc];
__device__ float g_wo[Dc * Dc];
__device__ float g_w1[Dc * DFFc];
__device__ float g_w2[DFFc * Dc];

// ---------------- helpers ----------------
__device__ __forceinline__ float rtf32(float x) { return wmma::__float_to_tf32(x); }

__device__ __forceinline__ void cp_async16(void* smem, const void* g) {
    uint32_t s = (uint32_t)__cvta_generic_to_shared(smem);
    asm volatile("cp.async.cg.shared.global [%0], [%1], 16;\n" :: "r"(s), "l"(g));
}
__device__ __forceinline__ void cp_commit() { asm volatile("cp.async.commit_group;\n"); }
template <int N>
__device__ __forceinline__ void cp_wait() { asm volatile("cp.async.wait_group %0;\n" :: "n"(N)); }

// ---------------- weight pre-round (one-shot, tiny) ----------------
__global__ void round_kernel(const float* __restrict__ in, float* __restrict__ out, int n4)
{
    int i = blockIdx.x * 256 + threadIdx.x;
    if (i < n4) {
        float4 v = reinterpret_cast<const float4*>(in)[i];
        v.x = rtf32(v.x); v.y = rtf32(v.y); v.z = rtf32(v.z); v.w = rtf32(v.w);
        reinterpret_cast<float4*>(out)[i] = v;
    }
}

// ---------------- LayerNorm: one warp per token (output tf32-rounded) ----------------
__global__ void ln_kernel(const float* __restrict__ in, const float* __restrict__ g,
                          const float* __restrict__ be, float* __restrict__ out, int trans)
{
    int tid = threadIdx.x, wid = tid >> 5, lane = tid & 31;
    int m = blockIdx.x * 8 + wid;
    const float* row;
    if (trans) {
        int bv = m >> 9, t = m & 511;
        int b = bv / Vc, v = bv % Vc;
        row = in + ((size_t)((b * Tc + t) * Vc + v)) * Dc;
    } else {
        row = in + (size_t)m * Dc;
    }
    float4 x4[4];
    float sum = 0.f, sq = 0.f;
#pragma unroll
    for (int j = 0; j < 4; j++) {
        x4[j] = reinterpret_cast<const float4*>(row)[lane + 32 * j];
        sum += x4[j].x + x4[j].y + x4[j].z + x4[j].w;
        sq  += x4[j].x * x4[j].x + x4[j].y * x4[j].y + x4[j].z * x4[j].z + x4[j].w * x4[j].w;
    }
#pragma unroll
    for (int o = 16; o > 0; o >>= 1) {
        sum += __shfl_xor_sync(0xffffffffu, sum, o);
        sq  += __shfl_xor_sync(0xffffffffu, sq,  o);
    }
    float mean = sum * (1.f / Dc);
    float var  = sq * (1.f / Dc) - mean * mean;
    float rstd = rsqrtf(var + 1e-5f);
    float* orow = out + (size_t)m * Dc;
#pragma unroll
    for (int j = 0; j < 4; j++) {
        int f4 = lane + 32 * j;
        float4 gv = reinterpret_cast<const float4*>(g)[f4];
        float4 bb = reinterpret_cast<const float4*>(be)[f4];
        float4 o;
        o.x = rtf32((x4[j].x - mean) * rstd * gv.x + bb.x);
        o.y = rtf32((x4[j].y - mean) * rstd * gv.y + bb.y);
        o.z = rtf32((x4[j].z - mean) * rstd * gv.z + bb.z);
        o.w = rtf32((x4[j].w - mean) * rstd * gv.w + bb.w);
        reinterpret_cast<float4*>(orow)[f4] = o;
    }
}

// ---------------- tf32 wmma GEMM, 3-stage cp.async ring ----------------
// All MMA operands are pre-rounded to tf32 -> no in-loop conversion.
// EPI 0: QKV -> out[((bv*H+h)*T+t)*DH+dh] = tf32(v + bias)
// EPI 1: Oproj -> out[m*D+n] = v + bias + x_src(transposed gather)   (fp32)
// EPI 2: FFN1  -> out[m*N+n] = tf32(gelu(v + bias))
// EPI 3: FFN2  -> d_out[((b*T+t)*V+v)*D+n] = v + bias + resid[m*D+n] (fp32)
constexpr int BM = 128, BN = 128, BKg = 32, NST = 3;
constexpr int ALD = 36, BLD = 136, SLDg = 136;
constexpr int ASTG = BM * ALD;           // 4608 floats per A stage
constexpr int BSTG = BKg * BLD;          // 4352 floats per B stage
constexpr size_t SMG = (size_t)NST * (ASTG + BSTG) * sizeof(float);   // 107520 B

template <int EPI>
__global__ void __launch_bounds__(256, 2)
gemm_kernel(const float* __restrict__ A, const float* __restrict__ B,
            int M, int N, int K,
            const float* __restrict__ bias,
            const float* __restrict__ aux,
            float* __restrict__ out)
{
    extern __shared__ float sm[];
    const int tid = threadIdx.x, wid = tid >> 5;
    const int wm = wid & 3, wn = wid >> 2;          // 4x2 warp grid, warp tile 32x64
    const int m0 = blockIdx.y * BM, n0 = blockIdx.x * BN;

    wmma::fragment<wmma::accumulator, 16, 16, 8, float> acc[2][4];
#pragma unroll
    for (int i = 0; i < 2; i++)
#pragma unroll
        for (int j = 0; j < 4; j++) wmma::fill_fragment(acc[i][j], 0.0f);

    auto load_stage = [&](int k0, int buf) {
        float* As = sm + buf * ASTG;
        float* Bs = sm + NST * ASTG + buf * BSTG;
#pragma unroll
        for (int i = 0; i < 4; i++) {
            int f = tid + 256 * i;
            int r = f >> 3, c4 = f & 7;
            cp_async16(As + r * ALD + c4 * 4, A + (size_t)(m0 + r) * K + k0 + c4 * 4);
        }
#pragma unroll
        for (int i = 0; i < 4; i++) {
            int f = tid + 256 * i;
            int r = f >> 5, c4 = f & 31;
            cp_async16(Bs + r * BLD + c4 * 4, B + (size_t)(k0 + r) * N + n0 + c4 * 4);
        }
    };

    const int nst = K / BKg;
    load_stage(0, 0); cp_commit();
    load_stage(BKg, 1); cp_commit();

    for (int s = 0; s < nst; s++) {
        if (s < nst - 1) cp_wait<1>(); else cp_wait<0>();
        __syncthreads();
        if (s + 2 < nst) { load_stage((s + 2) * BKg, (s + 2) % NST); cp_commit(); }

        const float* As = sm + (s % NST) * ASTG;
        const float* Bs = sm + NST * ASTG + (s % NST) * BSTG;
#pragma unroll
        for (int kk = 0; kk < BKg; kk += 8) {
            wmma::fragment<wmma::matrix_a, 16, 16, 8, wmma::precision::tf32, wmma::row_major> af[2];
            wmma::fragment<wmma::matrix_b, 16, 16, 8, wmma::precision::tf32, wmma::row_major> bf[4];
#pragma unroll
            for (int i = 0; i < 2; i++)
                wmma::load_matrix_sync(af[i], As + (wm * 32 + i * 16) * ALD + kk, ALD);
#pragma unroll
            for (int j = 0; j < 4; j++)
                wmma::load_matrix_sync(bf[j], Bs + kk * BLD + wn * 64 + j * 16, BLD);
#pragma unroll
            for (int i = 0; i < 2; i++)
#pragma unroll
                for (int j = 0; j < 4; j++)
                    wmma::mma_sync(acc[i][j], af[i], bf[j], acc[i][j]);
        }
    }
    __syncthreads();   // drain before reusing smem as the staging tile

    float* St = sm;                   // [128][136]
#pragma unroll
    for (int i = 0; i < 2; i++)
#pragma unroll
        for (int j = 0; j < 4; j++)
            wmma::store_matrix_sync(St + (wm * 32 + i * 16) * SLDg + wn * 64 + j * 16,
                                    acc[i][j], SLDg, wmma::mem_row_major);
    __syncthreads();

    for (int idx = tid; idx < BM * BN; idx += 256) {
        int r = idx >> 7, c = idx & 127;
        float v = St[r * SLDg + c];
        int gm = m0 + r, gn = n0 + c;
        v += bias[gn];
        if (EPI == 0) {
            int bv = gm >> 9, t = gm & 511, h = gn >> 6, dh = gn & 63;
            out[(((size_t)(bv * Hc + h) * Tc + t) << 6) + dh] = rtf32(v);
        } else if (EPI == 1) {
            int bv = gm >> 9, t = gm & 511, b = bv / Vc, vv = bv % Vc;
            v += aux[((size_t)((b * Tc + t) * Vc + vv) << 9) + gn];
            out[((size_t)gm << 9) + gn] = v;
        } else if (EPI == 2) {
            v = 0.5f * v * (1.0f + erff(v * 0.70710678118654752f));
            out[(size_t)gm * N + gn] = rtf32(v);
        } else {
            int bv = gm >> 9, t = gm & 511, b = bv / Vc, vv = bv % Vc;
            v += aux[((size_t)gm << 9) + gn];
            out[((size_t)((b * Tc + t) * Vc + vv) << 9) + gn] = v;
        }
    }
}

// ---------------- Attention v2: smem-staged, cp.async chunked ----------------
// Block = (bv, h, 32-query tile). 8 warps. K/V processed in 64-row chunks,
// double buffered. Q + scores + mask bias in smem. 2 CTAs/SM.
constexpr int QB = 32, CK = 64, KLD = 68, SLDa = 520;
constexpr int OS_S  = 0;                       // 32*520 = 16640 floats
constexpr int OS_Q  = QB * SLDa;               // 16640: Q 32x68 = 2176
constexpr int OS_KV = OS_Q + QB * KLD;         // 18816: 2 bufs x (64*68=4352)
constexpr int OS_MB = OS_KV + 2 * CK * KLD;    // 27520: 512 mask bias
constexpr size_t SMA = (size_t)(OS_MB + Tc) * sizeof(float);   // 112128 B

__global__ void __launch_bounds__(256, 2)
attn_kernel(const float* __restrict__ Q, const float* __restrict__ K,
            const float* __restrict__ V, const int* __restrict__ mask,
            float* __restrict__ out)
{
    extern __shared__ float f[];
    const int tid = threadIdx.x, wid = tid >> 5, lane = tid & 31;
    const int q0 = blockIdx.x * QB, h = blockIdx.y, bv = blockIdx.z, b = bv / Vc;
    const float* Qh = Q + (size_t)(bv * Hc + h) * Tc * DHc;
    const float* Kh = K + (size_t)(bv * Hc + h) * Tc * DHc;
    const float* Vh = V + (size_t)(bv * Hc + h) * Tc * DHc;
    const int tm = wid & 1, tn = wid >> 1;   // 2x4 warp tile grid over 32x64

    // group 0: Q tile (32x64) + K chunk 0 (64x64)
#pragma unroll
    for (int i = 0; i < 2; i++) {
        int fi = tid + 256 * i; int r = fi >> 4, c = fi & 15;
        cp_async16(f + OS_Q + r * KLD + c * 4, Qh + (size_t)(q0 + r) * DHc + c * 4);
    }
#pragma unroll
    for (int i = 0; i < 4; i++) {
        int fi = tid + 256 * i; int r = fi >> 4, c = fi & 15;
        cp_async16(f + OS_KV + r * KLD + c * 4, Kh + (size_t)r * DHc + c * 4);
    }
    cp_commit();
    // additive mask bias
    for (int j = tid; j < Tc; j += 256)
        f[OS_MB + j] = (mask[(size_t)b * Tc + j] != 0) ? 0.f : -INFINITY;

    // ---- Phase A: S = Q K^T / 8, 8 chunks of 64 keys ----
    for (int c = 0; c < 8; c++) {
        if (c + 1 < 8) {
            const float* src = Kh + (size_t)(c + 1) * CK * DHc;
            float* dst = f + OS_KV + ((c + 1) & 1) * (CK * KLD);
#pragma unroll
            for (int i = 0; i < 4; i++) {
                int fi = tid + 256 * i; int r = fi >> 4, cc = fi & 15;
                cp_async16(dst + r * KLD + cc * 4, src + (size_t)r * DHc + cc * 4);
            }
            cp_commit();
            cp_wait<1>();
        } else cp_wait<0>();
        __syncthreads();

        const float* kb = f + OS_KV + (c & 1) * (CK * KLD);
        wmma::fragment<wmma::accumulator, 16, 16, 8, float> acc;
        wmma::fill_fragment(acc, 0.0f);
#pragma unroll
        for (int kk = 0; kk < DHc; kk += 8) {
            wmma::fragment<wmma::matrix_a, 16, 16, 8, wmma::precision::tf32, wmma::row_major> af;
            wmma::fragment<wmma::matrix_b, 16, 16, 8, wmma::precision::tf32, wmma::col_major> bf;
            wmma::load_matrix_sync(af, f + OS_Q + (tm * 16) * KLD + kk, KLD);
            wmma::load_matrix_sync(bf, kb + (tn * 16) * KLD + kk, KLD);
            wmma::mma_sync(acc, af, bf, acc);
        }
#pragma unroll
        for (int e = 0; e < acc.num_elements; e++) acc.x[e] *= 0.125f;
        wmma::store_matrix_sync(f + OS_S + (tm * 16) * SLDa + c * 64 + tn * 16,
                                acc, SLDa, wmma::mem_row_major);
        __syncthreads();   // protect KV buffer reuse by next iteration's loads
    }

    // prefetch V chunk 0 under softmax (buf0 free: all warps past last sync)
    {
#pragma unroll
        for (int i = 0; i < 4; i++) {
            int fi = tid + 256 * i; int r = fi >> 4, cc = fi & 15;
            cp_async16(f + OS_KV + r * KLD + cc * 4, Vh + (size_t)r * DHc + cc * 4);
        }
        cp_commit();
    }

    // ---- softmax: each warp owns 4 rows, full-warp reductions ----
#pragma unroll
    for (int rr = 0; rr < 4; rr++) {
        int row = wid * 4 + rr;
        float* base = f + OS_S + row * SLDa;
        float vv[16];
        float mx = -INFINITY;
#pragma unroll
        for (int jj = 0; jj < 16; jj++) {
            int j = lane + 32 * jj;
            vv[jj] = base[j] + f[OS_MB + j];
            mx = fmaxf(mx, vv[jj]);
        }
#pragma unroll
        for (int o = 16; o > 0; o >>= 1) mx = fmaxf(mx, __shfl_xor_sync(0xffffffffu, mx, o));
        float sum = 0.f;
#pragma unroll
        for (int jj = 0; jj < 16; jj++) { vv[jj] = __expf(vv[jj] - mx); sum += vv[jj]; }
#pragma unroll
        for (int o = 16; o > 0; o >>= 1) sum += __shfl_xor_sync(0xffffffffu, sum, o);
        float inv = 1.f / sum;
#pragma unroll
        for (int jj = 0; jj < 16; jj++) base[lane + 32 * jj] = rtf32(vv[jj] * inv);
    }
    __syncthreads();

    // ---- Phase B: O = P V, 8 chunks of 64 keys, persistent accumulator ----
    wmma::fragment<wmma::accumulator, 16, 16, 8, float> accO;
    wmma::fill_fragment(accO, 0.0f);
    for (int c = 0; c < 8; c++) {
        if (c + 1 < 8) {
            const float* src = Vh + (size_t)(c + 1) * CK * DHc;
            float* dst = f + OS_KV + ((c + 1) & 1) * (CK * KLD);
#pragma unroll
            for (int i = 0; i < 4; i++) {
                int fi = tid + 256 * i; int r = fi >> 4, cc = fi & 15;
                cp_async16(dst + r * KLD + cc * 4, src + (size_t)r * DHc + cc * 4);
            }
            cp_commit();
            cp_wait<1>();
        } else cp_wait<0>();
        __syncthreads();

        const float* vb = f + OS_KV + (c & 1) * (CK * KLD);
#pragma unroll
        for (int kk = 0; kk < CK; kk += 8) {
            wmma::fragment<wmma::matrix_a, 16, 16, 8, wmma::precision::tf32, wmma::row_major> af;
            wmma::fragment<wmma::matrix_b, 16, 16, 8, wmma::precision::tf32, wmma::row_major> bf;
            wmma::load_matrix_sync(af, f + OS_S + (tm * 16) * SLDa + c * 64 + kk, SLDa);
            wmma::load_matrix_sync(bf, vb + kk * KLD + tn * 16, KLD);
            wmma::mma_sync(accO, af, bf, accO);
        }
        __syncthreads();   // protect KV buffer reuse
    }

    // output rounded (feeds O-projection GEMM A operand)
#pragma unroll
    for (int e = 0; e < accO.num_elements; e++) accO.x[e] = rtf32(accO.x[e]);
    float* optr = out + (size_t)(bv * Tc + q0 + tm * 16) * Dc + h * DHc + tn * 16;
    wmma::store_matrix_sync(optr, accO, Dc, wmma::mem_row_major);
}

// ---------------- launch ----------------
extern "C" void kernel_launch(void* const* d_in, const int* in_sizes, int n_in,
                              void* d_out, int out_size)
{
    const float* x  = (const float*)d_in[0];
    const int* mask = (const int*)d_in[1];          // bool -> int32 in harness
    const float* Wq = (const float*)d_in[2];
    const float* bq = (const float*)d_in[3];
    const float* Wk = (const float*)d_in[4];
    const float* bk = (const float*)d_in[5];
    const float* Wv = (const float*)d_in[6];
    const float* bvb = (const float*)d_in[7];
    const float* Wo = (const float*)d_in[8];
    const float* bo = (const float*)d_in[9];
    const float* W1 = (const float*)d_in[10];
    const float* b1 = (const float*)d_in[11];
    const float* W2 = (const float*)d_in[12];
    const float* b2 = (const float*)d_in[13];
    const float* g1 = (const float*)d_in[14];
    const float* be1 = (const float*)d_in[15];
    const float* g2 = (const float*)d_in[16];
    const float* be2 = (const float*)d_in[17];
    float* out = (float*)d_out;

    float *xn, *q, *k, *v, *xr, *ff, *wq, *wk, *wv, *wo, *w1, *w2;
    cudaGetSymbolAddress((void**)&xn, g_xn);
    cudaGetSymbolAddress((void**)&q,  g_q);
    cudaGetSymbolAddress((void**)&k,  g_k);
    cudaGetSymbolAddress((void**)&v,  g_v);
    cudaGetSymbolAddress((void**)&xr, g_xr);
    cudaGetSymbolAddress((void**)&ff, g_ff);
    cudaGetSymbolAddress((void**)&wq, g_wq);
    cudaGetSymbolAddress((void**)&wk, g_wk);
    cudaGetSymbolAddress((void**)&wv, g_wv);
    cudaGetSymbolAddress((void**)&wo, g_wo);
    cudaGetSymbolAddress((void**)&w1, g_w1);
    cudaGetSymbolAddress((void**)&w2, g_w2);

    cudaFuncSetAttribute(gemm_kernel<0>, cudaFuncAttributeMaxDynamicSharedMemorySize, (int)SMG);
    cudaFuncSetAttribute(gemm_kernel<1>, cudaFuncAttributeMaxDynamicSharedMemorySize, (int)SMG);
    cudaFuncSetAttribute(gemm_kernel<2>, cudaFuncAttributeMaxDynamicSharedMemorySize, (int)SMG);
    cudaFuncSetAttribute(gemm_kernel<3>, cudaFuncAttributeMaxDynamicSharedMemorySize, (int)SMG);
    cudaFuncSetAttribute(attn_kernel,    cudaFuncAttributeMaxDynamicSharedMemorySize, (int)SMA);

    // 0. pre-round weights to tf32 (one-shot, tiny)
    round_kernel<<<(Dc * Dc / 4 + 255) / 256, 256>>>(Wq, wq, Dc * Dc / 4);
    round_kernel<<<(Dc * Dc / 4 + 255) / 256, 256>>>(Wk, wk, Dc * Dc / 4);
    round_kernel<<<(Dc * Dc / 4 + 255) / 256, 256>>>(Wv, wv, Dc * Dc / 4);
    round_kernel<<<(Dc * Dc / 4 + 255) / 256, 256>>>(Wo, wo, Dc * Dc / 4);
    round_kernel<<<(Dc * DFFc / 4 + 255) / 256, 256>>>(W1, w1, Dc * DFFc / 4);
    round_kernel<<<(DFFc * Dc / 4 + 255) / 256, 256>>>(W2, w2, DFFc * Dc / 4);

    dim3 g512(Dc / BN, MTOK / BM);     // (4, 768)
    dim3 gff(DFFc / BN, MTOK / BM);    // (16, 768)

    // 1. LN1 (gather-transpose from x)
    ln_kernel<<<MTOK / 8, 256>>>(x, g1, be1, xn, 1);
    // 2. QKV projections -> head-major (BV, H, T, DH)
    gemm_kernel<0><<<g512, 256, SMG>>>(xn, wq, MTOK, Dc, Dc, bq,  nullptr, q);
    gemm_kernel<0><<<g512, 256, SMG>>>(xn, wk, MTOK, Dc, Dc, bk,  nullptr, k);
    gemm_kernel<0><<<g512, 256, SMG>>>(xn, wv, MTOK, Dc, Dc, bvb, nullptr, v);
    // 3. Attention -> xn (reused)
    attn_kernel<<<dim3(Tc / QB, Hc, BV), 256, SMA>>>(q, k, v, mask, xn);
    // 4. O-projection + residual (x gathered) -> xr
    gemm_kernel<1><<<g512, 256, SMG>>>(xn, wo, MTOK, Dc, Dc, bo, x, xr);
    // 5. LN2 -> q (reused as h)
    ln_kernel<<<MTOK / 8, 256>>>(xr, g2, be2, q, 0);
    // 6. FFN1 + bias + exact gelu -> ff
    gemm_kernel<2><<<gff, 256, SMG>>>(q, w1, MTOK, DFFc, Dc, b1, nullptr, ff);
    // 7. FFN2 + bias + residual + scatter-transpose -> d_out
    gemm_kernel<3><<<g512, 256, SMG>>>(ff, w2, MTOK, Dc, DFFc, b2, xr, out);
}

// round 11
// speedup vs baseline: 3.3384x; 2.0710x over previous
#include <cuda_runtime.h>
#include <cuda_fp16.h>
#include <mma.h>
#include <cstdint>
#include <cstddef>

using namespace nvcuda;

// Problem constants
constexpr int Bc = 8, Tc = 512, Vc = 24, Dc = 512, Hc = 8, DHc = 64, DFFc = 2048;
constexpr int BV = Bc * Vc;              // 192
constexpr int MTOK = BV * Tc;            // 98304 tokens

// ---------------- scratch (device globals; allocation-free rule) ----------------
__device__ __half g_xnh [(size_t)MTOK * Dc];    // LN1 out (half)
__device__ __half g_qh  [(size_t)MTOK * Dc];    // Q head-major (half)
__device__ __half g_kh  [(size_t)MTOK * Dc];
__device__ __half g_vh  [(size_t)MTOK * Dc];
__device__ __half g_ath [(size_t)MTOK * Dc];    // attention out (half)
__device__ __half g_h2h [(size_t)MTOK * Dc];    // LN2 out (half)
__device__ __half g_ffh [(size_t)MTOK * DFFc];  // FFN hidden (half)
__device__ float  g_xr  [(size_t)MTOK * Dc];    // residual stream (fp32)
// half weights, natural [K][N] layout
__device__ __half g_whq[Dc * Dc];
__device__ __half g_whk[Dc * Dc];
__device__ __half g_whv[Dc * Dc];
__device__ __half g_who[Dc * Dc];
__device__ __half g_wh1[Dc * DFFc];
__device__ __half g_wh2[DFFc * Dc];

// ---------------- helpers ----------------
__device__ __forceinline__ void cp_async16(void* smem, const void* g) {
    uint32_t s = (uint32_t)__cvta_generic_to_shared(smem);
    asm volatile("cp.async.cg.shared.global [%0], [%1], 16;\n" :: "r"(s), "l"(g));
}
__device__ __forceinline__ void cp_commit() { asm volatile("cp.async.commit_group;\n"); }
template <int N>
__device__ __forceinline__ void cp_wait() { asm volatile("cp.async.wait_group %0;\n" :: "n"(N)); }

// ---------------- weight fp32 -> fp16 (one-shot, tiny) ----------------
__global__ void wconv(const float* __restrict__ in, __half* __restrict__ out, int n4)
{
    int i = blockIdx.x * 256 + threadIdx.x;
    if (i < n4) {
        float4 v = reinterpret_cast<const float4*>(in)[i];
        __half2 a = __floats2half2_rn(v.x, v.y);
        __half2 b = __floats2half2_rn(v.z, v.w);
        reinterpret_cast<__half2*>(out)[i * 2]     = a;
        reinterpret_cast<__half2*>(out)[i * 2 + 1] = b;
    }
}

// ---------------- LayerNorm: one warp per token, half output ----------------
__global__ void ln_kernel(const float* __restrict__ in, const float* __restrict__ g,
                          const float* __restrict__ be, __half* __restrict__ out, int trans)
{
    int tid = threadIdx.x, wid = tid >> 5, lane = tid & 31;
    int m = blockIdx.x * 8 + wid;
    const float* row;
    if (trans) {
        int bv = m >> 9, t = m & 511;
        int b = bv / Vc, v = bv % Vc;
        row = in + ((size_t)((b * Tc + t) * Vc + v)) * Dc;
    } else {
        row = in + (size_t)m * Dc;
    }
    float4 x4[4];
    float sum = 0.f, sq = 0.f;
#pragma unroll
    for (int j = 0; j < 4; j++) {
        x4[j] = reinterpret_cast<const float4*>(row)[lane + 32 * j];
        sum += x4[j].x + x4[j].y + x4[j].z + x4[j].w;
        sq  += x4[j].x * x4[j].x + x4[j].y * x4[j].y + x4[j].z * x4[j].z + x4[j].w * x4[j].w;
    }
#pragma unroll
    for (int o = 16; o > 0; o >>= 1) {
        sum += __shfl_xor_sync(0xffffffffu, sum, o);
        sq  += __shfl_xor_sync(0xffffffffu, sq,  o);
    }
    float mean = sum * (1.f / Dc);
    float var  = sq * (1.f / Dc) - mean * mean;
    float rstd = rsqrtf(var + 1e-5f);
    __half2* orow = reinterpret_cast<__half2*>(out + (size_t)m * Dc);
#pragma unroll
    for (int j = 0; j < 4; j++) {
        int f4 = lane + 32 * j;
        float4 gv = reinterpret_cast<const float4*>(g)[f4];
        float4 bb = reinterpret_cast<const float4*>(be)[f4];
        float ox = (x4[j].x - mean) * rstd * gv.x + bb.x;
        float oy = (x4[j].y - mean) * rstd * gv.y + bb.y;
        float oz = (x4[j].z - mean) * rstd * gv.z + bb.z;
        float ow = (x4[j].w - mean) * rstd * gv.w + bb.w;
        orow[f4 * 2]     = __floats2half2_rn(ox, oy);
        orow[f4 * 2 + 1] = __floats2half2_rn(oz, ow);
    }
}

// ---------------- fp16 wmma GEMM, 3-stage cp.async ring ----------------
// C = A[MxK] * B[KxN], fp32 accumulate, fused epilogue.
// EPI 0: QKV -> outh[((bv*H+h)*T+t)*DH+dh] = half(v + bias)
// EPI 1: Oproj -> outf[m*D+n] = v + bias + x_src(transposed gather)
// EPI 2: FFN1  -> outh[m*N+n] = half(gelu(v + bias))
// EPI 3: FFN2  -> outf[((b*T+t)*V+v)*D+n] = v + bias + resid[m*D+n]
constexpr int BM = 128, BN = 128, BKg = 32, NST = 3;
constexpr int ALDh = 40, BLDh = 136, SLDg = 136;
constexpr int ASTGh = BM * ALDh;          // 5120 halves / stage
constexpr int BSTGh = BKg * BLDh;         // 4352 halves / stage
constexpr size_t SMH = (size_t)BM * SLDg * sizeof(float);   // 69632 B (>= pipeline 56832 B)

template <int EPI>
__global__ void __launch_bounds__(256, 2)
gemm_h(const __half* __restrict__ A, const __half* __restrict__ B,
       int M, int N, int K,
       const float* __restrict__ bias,
       const float* __restrict__ aux,
       float* __restrict__ outf, __half* __restrict__ outh)
{
    extern __shared__ char smraw[];
    __half* hbase = reinterpret_cast<__half*>(smraw);
    const int tid = threadIdx.x, wid = tid >> 5;
    const int wm = wid & 3, wn = wid >> 2;          // 4x2 warp grid, warp tile 32x64
    const int m0 = blockIdx.y * BM, n0 = blockIdx.x * BN;

    wmma::fragment<wmma::accumulator, 16, 16, 16, float> acc[2][4];
#pragma unroll
    for (int i = 0; i < 2; i++)
#pragma unroll
        for (int j = 0; j < 4; j++) wmma::fill_fragment(acc[i][j], 0.0f);

    auto load_stage = [&](int k0, int b) {
        __half* As = hbase + b * ASTGh;
        __half* Bs = hbase + NST * ASTGh + b * BSTGh;
#pragma unroll
        for (int i = 0; i < 2; i++) {               // A: 128x32 halves = 512 x 16B
            int f = tid + 256 * i;
            int r = f >> 2, c = f & 3;
            cp_async16(As + r * ALDh + c * 8, A + (size_t)(m0 + r) * K + k0 + c * 8);
        }
#pragma unroll
        for (int i = 0; i < 2; i++) {               // B: 32x128 halves = 512 x 16B
            int f = tid + 256 * i;
            int r = f >> 4, c = f & 15;
            cp_async16(Bs + r * BLDh + c * 8, B + (size_t)(k0 + r) * N + n0 + c * 8);
        }
    };

    const int nst = K / BKg;
    load_stage(0, 0); cp_commit();
    load_stage(BKg, 1); cp_commit();

    for (int s = 0; s < nst; s++) {
        if (s < nst - 1) cp_wait<1>(); else cp_wait<0>();
        __syncthreads();
        if (s + 2 < nst) { load_stage((s + 2) * BKg, (s + 2) % NST); cp_commit(); }

        const __half* As = hbase + (s % NST) * ASTGh;
        const __half* Bs = hbase + NST * ASTGh + (s % NST) * BSTGh;
#pragma unroll
        for (int kk = 0; kk < BKg; kk += 16) {
            wmma::fragment<wmma::matrix_a, 16, 16, 16, __half, wmma::row_major> af[2];
            wmma::fragment<wmma::matrix_b, 16, 16, 16, __half, wmma::row_major> bf[4];
#pragma unroll
            for (int i = 0; i < 2; i++)
                wmma::load_matrix_sync(af[i], As + (wm * 32 + i * 16) * ALDh + kk, ALDh);
#pragma unroll
            for (int j = 0; j < 4; j++)
                wmma::load_matrix_sync(bf[j], Bs + kk * BLDh + wn * 64 + j * 16, BLDh);
#pragma unroll
            for (int i = 0; i < 2; i++)
#pragma unroll
                for (int j = 0; j < 4; j++)
                    wmma::mma_sync(acc[i][j], af[i], bf[j], acc[i][j]);
        }
    }
    __syncthreads();   // drain before reusing smem as fp32 staging

    float* St = reinterpret_cast<float*>(smraw);    // [128][136]
#pragma unroll
    for (int i = 0; i < 2; i++)
#pragma unroll
        for (int j = 0; j < 4; j++)
            wmma::store_matrix_sync(St + (wm * 32 + i * 16) * SLDg + wn * 64 + j * 16,
                                    acc[i][j], SLDg, wmma::mem_row_major);
    __syncthreads();

    for (int idx = tid; idx < BM * BN; idx += 256) {
        int r = idx >> 7, c = idx & 127;
        float v = St[r * SLDg + c];
        int gm = m0 + r, gn = n0 + c;
        v += bias[gn];
        if (EPI == 0) {
            int bv = gm >> 9, t = gm & 511, h = gn >> 6, dh = gn & 63;
            outh[(((size_t)(bv * Hc + h) * Tc + t) << 6) + dh] = __float2half(v);
        } else if (EPI == 1) {
            int bv = gm >> 9, t = gm & 511, b2 = bv / Vc, vv = bv % Vc;
            v += aux[((size_t)((b2 * Tc + t) * Vc + vv) << 9) + gn];
            outf[((size_t)gm << 9) + gn] = v;
        } else if (EPI == 2) {
            v = 0.5f * v * (1.0f + erff(v * 0.70710678118654752f));
            outh[(size_t)gm * N + gn] = __float2half(v);
        } else {
            int bv = gm >> 9, t = gm & 511, b2 = bv / Vc, vv = bv % Vc;
            v += aux[((size_t)gm << 9) + gn];
            outf[((size_t)((b2 * Tc + t) * Vc + vv) << 9) + gn] = v;
        }
    }
}

// ---------------- Attention: fp16 operands, smem-staged, cp.async chunked ----------------
// Block = (bv, h, 32-query tile). 8 warps. Scores fp32 in smem; probs rewritten
// in-place as half (row stride 1040 halves over the same 520-float rows).
constexpr int QB = 32, CK = 64, KLDh = 72, SLDa = 520;
constexpr int OS_S  = 0;                         // 32*520 fp32
constexpr int OS_Q  = QB * SLDa;                 // 16640 (floats); Q: 32*72 halves = 1152 floats
constexpr int OS_KV = OS_Q + (QB * KLDh) / 2;    // 17792; KV: 2 x 64*72 halves = 4608 floats
constexpr int OS_MB = OS_KV + (2 * CK * KLDh) / 2;   // 22400
constexpr size_t SMA = (size_t)(OS_MB + Tc) * sizeof(float);   // 91648 B

__global__ void __launch_bounds__(256, 2)
attn_kernel(const __half* __restrict__ Q, const __half* __restrict__ K,
            const __half* __restrict__ V, const int* __restrict__ mask,
            __half* __restrict__ out)
{
    extern __shared__ float f[];
    __half* hq  = reinterpret_cast<__half*>(f + OS_Q);
    __half* hkv = reinterpret_cast<__half*>(f + OS_KV);
    __half* hp  = reinterpret_cast<__half*>(f);          // probs overlay on scores
    const int tid = threadIdx.x, wid = tid >> 5, lane = tid & 31;
    const int q0 = blockIdx.x * QB, h = blockIdx.y, bv = blockIdx.z, b = bv / Vc;
    const __half* Qh = Q + (size_t)(bv * Hc + h) * Tc * DHc;
    const __half* Kh = K + (size_t)(bv * Hc + h) * Tc * DHc;
    const __half* Vh = V + (size_t)(bv * Hc + h) * Tc * DHc;
    const int tm = wid & 1, tn = wid >> 1;   // 2x4 warp tiles over 32x64

    // Q tile (32x64 halves = 256 x 16B) + K chunk 0 (64x64 halves = 512 x 16B)
    if (tid < 256) {
        int r = tid >> 3, c = tid & 7;
        cp_async16(hq + r * KLDh + c * 8, Qh + (size_t)(q0 + r) * DHc + c * 8);
    }
#pragma unroll
    for (int i = 0; i < 2; i++) {
        int fi = tid + 256 * i; int r = fi >> 3, c = fi & 7;
        cp_async16(hkv + r * KLDh + c * 8, Kh + (size_t)r * DHc + c * 8);
    }
    cp_commit();
    for (int j = tid; j < Tc; j += 256)
        f[OS_MB + j] = (mask[(size_t)b * Tc + j] != 0) ? 0.f : -INFINITY;

    // ---- Phase A: S = Q K^T / 8, 8 chunks of 64 keys ----
    for (int c = 0; c < 8; c++) {
        if (c + 1 < 8) {
            const __half* src = Kh + (size_t)(c + 1) * CK * DHc;
            __half* dst = hkv + ((c + 1) & 1) * (CK * KLDh);
#pragma unroll
            for (int i = 0; i < 2; i++) {
                int fi = tid + 256 * i; int r = fi >> 3, cc = fi & 7;
                cp_async16(dst + r * KLDh + cc * 8, src + (size_t)r * DHc + cc * 8);
            }
            cp_commit();
            cp_wait<1>();
        } else cp_wait<0>();
        __syncthreads();

        const __half* kb = hkv + (c & 1) * (CK * KLDh);
        wmma::fragment<wmma::accumulator, 16, 16, 16, float> acc;
        wmma::fill_fragment(acc, 0.0f);
#pragma unroll
        for (int kk = 0; kk < DHc; kk += 16) {
            wmma::fragment<wmma::matrix_a, 16, 16, 16, __half, wmma::row_major> af;
            wmma::fragment<wmma::matrix_b, 16, 16, 16, __half, wmma::col_major> bf;
            wmma::load_matrix_sync(af, hq + (tm * 16) * KLDh + kk, KLDh);
            wmma::load_matrix_sync(bf, kb + (tn * 16) * KLDh + kk, KLDh);
            wmma::mma_sync(acc, af, bf, acc);
        }
#pragma unroll
        for (int e = 0; e < acc.num_elements; e++) acc.x[e] *= 0.125f;
        wmma::store_matrix_sync(f + OS_S + (tm * 16) * SLDa + c * 64 + tn * 16,
                                acc, SLDa, wmma::mem_row_major);
        __syncthreads();
    }

    // prefetch V chunk 0 under softmax
#pragma unroll
    for (int i = 0; i < 2; i++) {
        int fi = tid + 256 * i; int r = fi >> 3, cc = fi & 7;
        cp_async16(hkv + r * KLDh + cc * 8, Vh + (size_t)r * DHc + cc * 8);
    }
    cp_commit();

    // ---- softmax: each warp owns 4 rows; probs written back as half ----
#pragma unroll
    for (int rr = 0; rr < 4; rr++) {
        int row = wid * 4 + rr;
        float* basep = f + OS_S + row * SLDa;
        float vv[16];
        float mx = -INFINITY;
#pragma unroll
        for (int jj = 0; jj < 16; jj++) {
            int j = lane + 32 * jj;
            vv[jj] = basep[j] + f[OS_MB + j];
            mx = fmaxf(mx, vv[jj]);
        }
#pragma unroll
        for (int o = 16; o > 0; o >>= 1) mx = fmaxf(mx, __shfl_xor_sync(0xffffffffu, mx, o));
        float sum = 0.f;
#pragma unroll
        for (int jj = 0; jj < 16; jj++) { vv[jj] = __expf(vv[jj] - mx); sum += vv[jj]; }
#pragma unroll
        for (int o = 16; o > 0; o >>= 1) sum += __shfl_xor_sync(0xffffffffu, sum, o);
        float inv = 1.f / sum;
        __half* hrow = hp + (size_t)row * (SLDa * 2);
#pragma unroll
        for (int jj = 0; jj < 16; jj++) hrow[lane + 32 * jj] = __float2half(vv[jj] * inv);
    }
    __syncthreads();

    // ---- Phase B: O = P V, 8 chunks of 64 keys ----
    wmma::fragment<wmma::accumulator, 16, 16, 16, float> accO;
    wmma::fill_fragment(accO, 0.0f);
    for (int c = 0; c < 8; c++) {
        if (c + 1 < 8) {
            const __half* src = Vh + (size_t)(c + 1) * CK * DHc;
            __half* dst = hkv + ((c + 1) & 1) * (CK * KLDh);
#pragma unroll
            for (int i = 0; i < 2; i++) {
                int fi = tid + 256 * i; int r = fi >> 3, cc = fi & 7;
                cp_async16(dst + r * KLDh + cc * 8, src + (size_t)r * DHc + cc * 8);
            }
            cp_commit();
            cp_wait<1>();
        } else cp_wait<0>();
        __syncthreads();

        const __half* vb = hkv + (c & 1) * (CK * KLDh);
#pragma unroll
        for (int kk = 0; kk < CK; kk += 16) {
            wmma::fragment<wmma::matrix_a, 16, 16, 16, __half, wmma::row_major> af;
            wmma::fragment<wmma::matrix_b, 16, 16, 16, __half, wmma::row_major> bf;
            wmma::load_matrix_sync(af, hp + (size_t)(tm * 16) * (SLDa * 2) + c * 64 + kk,
                                   SLDa * 2);
            wmma::load_matrix_sync(bf, vb + kk * KLDh + tn * 16, KLDh);
            wmma::mma_sync(accO, af, bf, accO);
        }
        __syncthreads();
    }

    // stage 32x64 fp32 result, convert to half, coalesced store
    float* St2 = f + OS_S;          // [32][68]
    wmma::store_matrix_sync(St2 + (tm * 16) * 68 + tn * 16, accO, 68, wmma::mem_row_major);
    __syncthreads();
    for (int idx = tid; idx < QB * 64; idx += 256) {
        int r = idx >> 6, c = idx & 63;
        out[(size_t)(bv * Tc + q0 + r) * Dc + h * DHc + c] = __float2half(St2[r * 68 + c]);
    }
}

// ---------------- launch ----------------
extern "C" void kernel_launch(void* const* d_in, const int* in_sizes, int n_in,
                              void* d_out, int out_size)
{
    const float* x  = (const float*)d_in[0];
    const int* mask = (const int*)d_in[1];          // bool -> int32 in harness
    const float* Wq = (const float*)d_in[2];
    const float* bq = (const float*)d_in[3];
    const float* Wk = (const float*)d_in[4];
    const float* bk = (const float*)d_in[5];
    const float* Wv = (const float*)d_in[6];
    const float* bvb = (const float*)d_in[7];
    const float* Wo = (const float*)d_in[8];
    const float* bo = (const float*)d_in[9];
    const float* W1 = (const float*)d_in[10];
    const float* b1 = (const float*)d_in[11];
    const float* W2 = (const float*)d_in[12];
    const float* b2 = (const float*)d_in[13];
    const float* g1 = (const float*)d_in[14];
    const float* be1 = (const float*)d_in[15];
    const float* g2 = (const float*)d_in[16];
    const float* be2 = (const float*)d_in[17];
    float* out = (float*)d_out;

    __half *xnh, *qh, *kh, *vh, *ath, *h2h, *ffh, *whq, *whk, *whv, *who, *wh1, *wh2;
    float *xr;
    cudaGetSymbolAddress((void**)&xnh, g_xnh);
    cudaGetSymbolAddress((void**)&qh,  g_qh);
    cudaGetSymbolAddress((void**)&kh,  g_kh);
    cudaGetSymbolAddress((void**)&vh,  g_vh);
    cudaGetSymbolAddress((void**)&ath, g_ath);
    cudaGetSymbolAddress((void**)&h2h, g_h2h);
    cudaGetSymbolAddress((void**)&ffh, g_ffh);
    cudaGetSymbolAddress((void**)&xr,  g_xr);
    cudaGetSymbolAddress((void**)&whq, g_whq);
    cudaGetSymbolAddress((void**)&whk, g_whk);
    cudaGetSymbolAddress((void**)&whv, g_whv);
    cudaGetSymbolAddress((void**)&who, g_who);
    cudaGetSymbolAddress((void**)&wh1, g_wh1);
    cudaGetSymbolAddress((void**)&wh2, g_wh2);

    cudaFuncSetAttribute(gemm_h<0>, cudaFuncAttributeMaxDynamicSharedMemorySize, (int)SMH);
    cudaFuncSetAttribute(gemm_h<1>, cudaFuncAttributeMaxDynamicSharedMemorySize, (int)SMH);
    cudaFuncSetAttribute(gemm_h<2>, cudaFuncAttributeMaxDynamicSharedMemorySize, (int)SMH);
    cudaFuncSetAttribute(gemm_h<3>, cudaFuncAttributeMaxDynamicSharedMemorySize, (int)SMH);
    cudaFuncSetAttribute(attn_kernel, cudaFuncAttributeMaxDynamicSharedMemorySize, (int)SMA);

    // 0. weights fp32 -> fp16 (natural [K][N] layout, no transpose)
    wconv<<<Dc * Dc / 4 / 256, 256>>>(Wq, whq, Dc * Dc / 4);
    wconv<<<Dc * Dc / 4 / 256, 256>>>(Wk, whk, Dc * Dc / 4);
    wconv<<<Dc * Dc / 4 / 256, 256>>>(Wv, whv, Dc * Dc / 4);
    wconv<<<Dc * Dc / 4 / 256, 256>>>(Wo, who, Dc * Dc / 4);
    wconv<<<Dc * DFFc / 4 / 256, 256>>>(W1, wh1, Dc * DFFc / 4);
    wconv<<<DFFc * Dc / 4 / 256, 256>>>(W2, wh2, DFFc * Dc / 4);

    dim3 g512(Dc / BN, MTOK / BM);     // (4, 768)
    dim3 gff(DFFc / BN, MTOK / BM);    // (16, 768)

    // 1. LN1 (gather-transpose from x) -> half
    ln_kernel<<<MTOK / 8, 256>>>(x, g1, be1, xnh, 1);
    // 2. QKV projections -> head-major half
    gemm_h<0><<<g512, 256, SMH>>>(xnh, whq, MTOK, Dc, Dc, bq,  nullptr, nullptr, qh);
    gemm_h<0><<<g512, 256, SMH>>>(xnh, whk, MTOK, Dc, Dc, bk,  nullptr, nullptr, kh);
    gemm_h<0><<<g512, 256, SMH>>>(xnh, whv, MTOK, Dc, Dc, bvb, nullptr, nullptr, vh);
    // 3. Attention -> half
    attn_kernel<<<dim3(Tc / QB, Hc, BV), 256, SMA>>>(qh, kh, vh, mask, ath);
    // 4. O-projection + residual (x gathered) -> xr fp32
    gemm_h<1><<<g512, 256, SMH>>>(ath, who, MTOK, Dc, Dc, bo, x, xr, nullptr);
    // 5. LN2 -> half
    ln_kernel<<<MTOK / 8, 256>>>(xr, g2, be2, h2h, 0);
    // 6. FFN1 + bias + exact gelu -> half
    gemm_h<2><<<gff, 256, SMH>>>(h2h, wh1, MTOK, DFFc, Dc, b1, nullptr, nullptr, ffh);
    // 7. FFN2 + bias + residual + scatter-transpose -> fp32 d_out
    gemm_h<3><<<g512, 256, SMH>>>(ffh, wh2, MTOK, Dc, DFFc, b2, xr, out, nullptr);
}

// round 12
// speedup vs baseline: 5.2660x; 1.5774x over previous
#include <cuda_runtime.h>
#include <cuda_fp16.h>
#include <mma.h>
#include <cstdint>
#include <cstddef>

using namespace nvcuda;

// Problem constants
constexpr int Bc = 8, Tc = 512, Vc = 24, Dc = 512, Hc = 8, DHc = 64, DFFc = 2048;
constexpr int BV = Bc * Vc;              // 192
constexpr int MTOK = BV * Tc;            // 98304 tokens

// ---------------- scratch (device globals; allocation-free rule) ----------------
__device__ __half g_xnh [(size_t)MTOK * Dc];    // LN1 out (half)
__device__ __half g_qh  [(size_t)MTOK * Dc];    // Q head-major (half)
__device__ __half g_kh  [(size_t)MTOK * Dc];
__device__ __half g_vh  [(size_t)MTOK * Dc];
__device__ __half g_ath [(size_t)MTOK * Dc];    // attention out (half)
__device__ __half g_h2h [(size_t)MTOK * Dc];    // LN2 out (half)
__device__ __half g_ffh [(size_t)MTOK * DFFc];  // FFN hidden (half)
__device__ float  g_xr  [(size_t)MTOK * Dc];    // residual stream (fp32)
// half weights
__device__ __half g_wqkv[Dc * 3 * Dc];          // [K=512][N=1536] concat Q|K|V
__device__ float  g_bqkv[3 * Dc];               // concat biases
__device__ __half g_who[Dc * Dc];
__device__ __half g_wh1[Dc * DFFc];
__device__ __half g_wh2[DFFc * Dc];

// ---------------- helpers ----------------
__device__ __forceinline__ void cp_async16(void* smem, const void* g) {
    uint32_t s = (uint32_t)__cvta_generic_to_shared(smem);
    asm volatile("cp.async.cg.shared.global [%0], [%1], 16;\n" :: "r"(s), "l"(g));
}
__device__ __forceinline__ void cp_commit() { asm volatile("cp.async.commit_group;\n"); }
template <int N>
__device__ __forceinline__ void cp_wait() { asm volatile("cp.async.wait_group %0;\n" :: "n"(N)); }

// ---------------- weight fp32 -> fp16 (one-shot, tiny) ----------------
__global__ void wconv(const float* __restrict__ in, __half* __restrict__ out, int n4)
{
    int i = blockIdx.x * 256 + threadIdx.x;
    if (i < n4) {
        float4 v = reinterpret_cast<const float4*>(in)[i];
        reinterpret_cast<__half2*>(out)[i * 2]     = __floats2half2_rn(v.x, v.y);
        reinterpret_cast<__half2*>(out)[i * 2 + 1] = __floats2half2_rn(v.z, v.w);
    }
}
// in [512][512] -> out rows of ld=1536 at column offset off
__global__ void wconv_off(const float* __restrict__ in, __half* __restrict__ out,
                          int off)
{
    int i = blockIdx.x * 256 + threadIdx.x;   // over 512*512/4
    if (i < Dc * Dc / 4) {
        int k = (i * 4) >> 9, n = (i * 4) & 511;
        float4 v = reinterpret_cast<const float4*>(in)[i];
        __half2* o = reinterpret_cast<__half2*>(out + (size_t)k * (3 * Dc) + off + n);
        o[0] = __floats2half2_rn(v.x, v.y);
        o[1] = __floats2half2_rn(v.z, v.w);
    }
}
__global__ void bcat(const float* __restrict__ a, const float* __restrict__ b,
                     const float* __restrict__ c, float* __restrict__ o)
{
    int i = blockIdx.x * 256 + threadIdx.x;
    if (i < Dc) { o[i] = a[i]; o[Dc + i] = b[i]; o[2 * Dc + i] = c[i]; }
}

// ---------------- LayerNorm: one warp per token, half output ----------------
__global__ void ln_kernel(const float* __restrict__ in, const float* __restrict__ g,
                          const float* __restrict__ be, __half* __restrict__ out, int trans)
{
    int tid = threadIdx.x, wid = tid >> 5, lane = tid & 31;
    int m = blockIdx.x * 8 + wid;
    const float* row;
    if (trans) {
        int bv = m >> 9, t = m & 511;
        int b = bv / Vc, v = bv % Vc;
        row = in + ((size_t)((b * Tc + t) * Vc + v)) * Dc;
    } else {
        row = in + (size_t)m * Dc;
    }
    float4 x4[4];
    float sum = 0.f, sq = 0.f;
#pragma unroll
    for (int j = 0; j < 4; j++) {
        x4[j] = reinterpret_cast<const float4*>(row)[lane + 32 * j];
        sum += x4[j].x + x4[j].y + x4[j].z + x4[j].w;
        sq  += x4[j].x * x4[j].x + x4[j].y * x4[j].y + x4[j].z * x4[j].z + x4[j].w * x4[j].w;
    }
#pragma unroll
    for (int o = 16; o > 0; o >>= 1) {
        sum += __shfl_xor_sync(0xffffffffu, sum, o);
        sq  += __shfl_xor_sync(0xffffffffu, sq,  o);
    }
    float mean = sum * (1.f / Dc);
    float var  = sq * (1.f / Dc) - mean * mean;
    float rstd = rsqrtf(var + 1e-5f);
    __half2* orow = reinterpret_cast<__half2*>(out + (size_t)m * Dc);
#pragma unroll
    for (int j = 0; j < 4; j++) {
        int f4 = lane + 32 * j;
        float4 gv = reinterpret_cast<const float4*>(g)[f4];
        float4 bb = reinterpret_cast<const float4*>(be)[f4];
        float ox = (x4[j].x - mean) * rstd * gv.x + bb.x;
        float oy = (x4[j].y - mean) * rstd * gv.y + bb.y;
        float oz = (x4[j].z - mean) * rstd * gv.z + bb.z;
        float ow = (x4[j].w - mean) * rstd * gv.w + bb.w;
        orow[f4 * 2]     = __floats2half2_rn(ox, oy);
        orow[f4 * 2 + 1] = __floats2half2_rn(oz, ow);
    }
}

// ---------------- fp16 wmma GEMM, 3-stage cp.async ring, BK=64 ----------------
// EPI 0: merged QKV (N=1536) -> q/k/v head-major half
// EPI 1: Oproj -> outf[m*D+n] = v + bias + x_src(transposed gather)
// EPI 2: FFN1  -> outh[m*N+n] = half(gelu(v + bias))
// EPI 3: FFN2  -> outf[((b*T+t)*V+v)*D+n] = v + bias + resid[m*D+n]
constexpr int BM = 128, BN = 128, BKg = 64, NST = 3;
constexpr int ALDh = 72, BLDh = 136, SLDg = 136;
constexpr int ASTGh = BM * ALDh;          // 9216 halves / stage
constexpr int BSTGh = BKg * BLDh;         // 8704 halves / stage
constexpr size_t SMH = (size_t)NST * (ASTGh + BSTGh) * sizeof(__half);   // 107520 B

template <int EPI>
__global__ void __launch_bounds__(256, 2)
gemm_h(const __half* __restrict__ A, const __half* __restrict__ B,
       int M, int N, int K,
       const float* __restrict__ bias,
       const float* __restrict__ aux,
       float* __restrict__ outf, __half* __restrict__ outh,
       __half* __restrict__ outh2, __half* __restrict__ outh3)
{
    extern __shared__ char smraw[];
    __half* hbase = reinterpret_cast<__half*>(smraw);
    const int tid = threadIdx.x, wid = tid >> 5;
    const int wm = wid & 3, wn = wid >> 2;          // 4x2 warp grid, warp tile 32x64
    const int m0 = blockIdx.y * BM, n0 = blockIdx.x * BN;

    wmma::fragment<wmma::accumulator, 16, 16, 16, float> acc[2][4];
#pragma unroll
    for (int i = 0; i < 2; i++)
#pragma unroll
        for (int j = 0; j < 4; j++) wmma::fill_fragment(acc[i][j], 0.0f);

    auto load_stage = [&](int k0, int b) {
        __half* As = hbase + b * ASTGh;
        __half* Bs = hbase + NST * ASTGh + b * BSTGh;
#pragma unroll
        for (int i = 0; i < 4; i++) {               // A: 128x64 halves = 1024 x 16B
            int f = tid + 256 * i;
            int r = f >> 3, c = f & 7;
            cp_async16(As + r * ALDh + c * 8, A + (size_t)(m0 + r) * K + k0 + c * 8);
        }
#pragma unroll
        for (int i = 0; i < 4; i++) {               // B: 64x128 halves = 1024 x 16B
            int f = tid + 256 * i;
            int r = f >> 4, c = f & 15;
            cp_async16(Bs + r * BLDh + c * 8, B + (size_t)(k0 + r) * N + n0 + c * 8);
        }
    };

    const int nst = K / BKg;
    load_stage(0, 0); cp_commit();
    load_stage(BKg, 1); cp_commit();

    for (int s = 0; s < nst; s++) {
        if (s < nst - 1) cp_wait<1>(); else cp_wait<0>();
        __syncthreads();
        if (s + 2 < nst) { load_stage((s + 2) * BKg, (s + 2) % NST); cp_commit(); }

        const __half* As = hbase + (s % NST) * ASTGh;
        const __half* Bs = hbase + NST * ASTGh + (s % NST) * BSTGh;
#pragma unroll
        for (int kk = 0; kk < BKg; kk += 16) {
            wmma::fragment<wmma::matrix_a, 16, 16, 16, __half, wmma::row_major> af[2];
            wmma::fragment<wmma::matrix_b, 16, 16, 16, __half, wmma::row_major> bf[4];
#pragma unroll
            for (int i = 0; i < 2; i++)
                wmma::load_matrix_sync(af[i], As + (wm * 32 + i * 16) * ALDh + kk, ALDh);
#pragma unroll
            for (int j = 0; j < 4; j++)
                wmma::load_matrix_sync(bf[j], Bs + kk * BLDh + wn * 64 + j * 16, BLDh);
#pragma unroll
            for (int i = 0; i < 2; i++)
#pragma unroll
                for (int j = 0; j < 4; j++)
                    wmma::mma_sync(acc[i][j], af[i], bf[j], acc[i][j]);
        }
    }
    __syncthreads();   // drain before reusing smem as fp32 staging

    float* St = reinterpret_cast<float*>(smraw);    // [128][136]
#pragma unroll
    for (int i = 0; i < 2; i++)
#pragma unroll
        for (int j = 0; j < 4; j++)
            wmma::store_matrix_sync(St + (wm * 32 + i * 16) * SLDg + wn * 64 + j * 16,
                                    acc[i][j], SLDg, wmma::mem_row_major);
    __syncthreads();

    for (int idx = tid; idx < BM * BN; idx += 256) {
        int r = idx >> 7, c = idx & 127;
        float v = St[r * SLDg + c];
        int gm = m0 + r, gn = n0 + c;
        v += bias[gn];
        if (EPI == 0) {
            int bv = gm >> 9, t = gm & 511;
            int which = gn >> 9, n = gn & 511, h = n >> 6, dh = n & 63;
            __half* dst = (which == 0) ? outh : (which == 1) ? outh2 : outh3;
            dst[(((size_t)(bv * Hc + h) * Tc + t) << 6) + dh] = __float2half(v);
        } else if (EPI == 1) {
            int bv = gm >> 9, t = gm & 511, b2 = bv / Vc, vv = bv % Vc;
            v += aux[((size_t)((b2 * Tc + t) * Vc + vv) << 9) + gn];
            outf[((size_t)gm << 9) + gn] = v;
        } else if (EPI == 2) {
            v = 0.5f * v * (1.0f + erff(v * 0.70710678118654752f));
            outh[(size_t)gm * N + gn] = __float2half(v);
        } else {
            int bv = gm >> 9, t = gm & 511, b2 = bv / Vc, vv = bv % Vc;
            v += aux[((size_t)gm << 9) + gn];
            outf[((size_t)((b2 * Tc + t) * Vc + vv) << 9) + gn] = v;
        }
    }
}

// ---------------- Attention: fp16 operands, 128-row K/V chunks ----------------
// Block = (bv, h, 32-query tile). 8 warps. Scores fp32 in smem; probs rewritten
// in-place as half (overlay stride 1040 halves over the 520-float rows).
constexpr int QB = 32, CK = 128, KLDh = 72, SLDa = 520;
constexpr int OS_S  = 0;                           // 32*520 fp32
constexpr int OS_Q  = QB * SLDa;                   // Q: 32*72 halves = 1152 floats
constexpr int OS_KV = OS_Q + (QB * KLDh) / 2;      // KV: 2 x 128*72 halves = 9216 floats
constexpr int OS_MB = OS_KV + (2 * CK * KLDh) / 2;
constexpr size_t SMA = (size_t)(OS_MB + Tc) * sizeof(float);   // 110080 B

__global__ void __launch_bounds__(256, 2)
attn_kernel(const __half* __restrict__ Q, const __half* __restrict__ K,
            const __half* __restrict__ V, const int* __restrict__ mask,
            __half* __restrict__ out)
{
    extern __shared__ float f[];
    __half* hq  = reinterpret_cast<__half*>(f + OS_Q);
    __half* hkv = reinterpret_cast<__half*>(f + OS_KV);
    __half* hp  = reinterpret_cast<__half*>(f);          // probs overlay on scores
    const int tid = threadIdx.x, wid = tid >> 5, lane = tid & 31;
    const int q0 = blockIdx.x * QB, h = blockIdx.y, bv = blockIdx.z, b = bv / Vc;
    const __half* Qh = Q + (size_t)(bv * Hc + h) * Tc * DHc;
    const __half* Kh = K + (size_t)(bv * Hc + h) * Tc * DHc;
    const __half* Vh = V + (size_t)(bv * Hc + h) * Tc * DHc;
    const int tm = wid & 1, tn = wid >> 1;   // 2x4 warp tiles over 32x64

    // Q tile (32x64 halves) + K chunk 0 (128x64 halves = 1024 x 16B)
    if (tid < 256) {
        int r = tid >> 3, c = tid & 7;
        cp_async16(hq + r * KLDh + c * 8, Qh + (size_t)(q0 + r) * DHc + c * 8);
    }
#pragma unroll
    for (int i = 0; i < 4; i++) {
        int fi = tid + 256 * i; int r = fi >> 3, c = fi & 7;
        cp_async16(hkv + r * KLDh + c * 8, Kh + (size_t)r * DHc + c * 8);
    }
    cp_commit();
    for (int j = tid; j < Tc; j += 256)
        f[OS_MB + j] = (mask[(size_t)b * Tc + j] != 0) ? 0.f : -INFINITY;

    // ---- Phase A: S = Q K^T / 8, 4 chunks of 128 keys ----
    for (int c = 0; c < 4; c++) {
        if (c + 1 < 4) {
            const __half* src = Kh + (size_t)(c + 1) * CK * DHc;
            __half* dst = hkv + ((c + 1) & 1) * (CK * KLDh);
#pragma unroll
            for (int i = 0; i < 4; i++) {
                int fi = tid + 256 * i; int r = fi >> 3, cc = fi & 7;
                cp_async16(dst + r * KLDh + cc * 8, src + (size_t)r * DHc + cc * 8);
            }
            cp_commit();
            cp_wait<1>();
        } else cp_wait<0>();
        __syncthreads();

        const __half* kb = hkv + (c & 1) * (CK * KLDh);
        // each warp: 16 rows x two 16-col subtiles (covers 32x128 per chunk)
#pragma unroll
        for (int sub = 0; sub < 2; sub++) {
            wmma::fragment<wmma::accumulator, 16, 16, 16, float> acc;
            wmma::fill_fragment(acc, 0.0f);
#pragma unroll
            for (int kk = 0; kk < DHc; kk += 16) {
                wmma::fragment<wmma::matrix_a, 16, 16, 16, __half, wmma::row_major> af;
                wmma::fragment<wmma::matrix_b, 16, 16, 16, __half, wmma::col_major> bf;
                wmma::load_matrix_sync(af, hq + (tm * 16) * KLDh + kk, KLDh);
                wmma::load_matrix_sync(bf, kb + (tn * 32 + sub * 16) * KLDh + kk, KLDh);
                wmma::mma_sync(acc, af, bf, acc);
            }
#pragma unroll
            for (int e = 0; e < acc.num_elements; e++) acc.x[e] *= 0.125f;
            wmma::store_matrix_sync(f + OS_S + (tm * 16) * SLDa + c * 128 + tn * 32 + sub * 16,
                                    acc, SLDa, wmma::mem_row_major);
        }
        __syncthreads();
    }

    // prefetch V chunk 0 under softmax
#pragma unroll
    for (int i = 0; i < 4; i++) {
        int fi = tid + 256 * i; int r = fi >> 3, cc = fi & 7;
        cp_async16(hkv + r * KLDh + cc * 8, Vh + (size_t)r * DHc + cc * 8);
    }
    cp_commit();

    // ---- softmax: each warp owns 4 rows; probs written back as half ----
#pragma unroll
    for (int rr = 0; rr < 4; rr++) {
        int row = wid * 4 + rr;
        float* basep = f + OS_S + row * SLDa;
        float vv[16];
        float mx = -INFINITY;
#pragma unroll
        for (int jj = 0; jj < 16; jj++) {
            int j = lane + 32 * jj;
            vv[jj] = basep[j] + f[OS_MB + j];
            mx = fmaxf(mx, vv[jj]);
        }
#pragma unroll
        for (int o = 16; o > 0; o >>= 1) mx = fmaxf(mx, __shfl_xor_sync(0xffffffffu, mx, o));
        float sum = 0.f;
#pragma unroll
        for (int jj = 0; jj < 16; jj++) { vv[jj] = __expf(vv[jj] - mx); sum += vv[jj]; }
#pragma unroll
        for (int o = 16; o > 0; o >>= 1) sum += __shfl_xor_sync(0xffffffffu, sum, o);
        float inv = 1.f / sum;
        __half* hrow = hp + (size_t)row * (SLDa * 2);
#pragma unroll
        for (int jj = 0; jj < 16; jj++) hrow[lane + 32 * jj] = __float2half(vv[jj] * inv);
    }
    __syncthreads();

    // ---- Phase B: O = P V, 4 chunks of 128 keys ----
    wmma::fragment<wmma::accumulator, 16, 16, 16, float> accO;
    wmma::fill_fragment(accO, 0.0f);
    for (int c = 0; c < 4; c++) {
        if (c + 1 < 4) {
            const __half* src = Vh + (size_t)(c + 1) * CK * DHc;
            __half* dst = hkv + ((c + 1) & 1) * (CK * KLDh);
#pragma unroll
            for (int i = 0; i < 4; i++) {
                int fi = tid + 256 * i; int r = fi >> 3, cc = fi & 7;
                cp_async16(dst + r * KLDh + cc * 8, src + (size_t)r * DHc + cc * 8);
            }
            cp_commit();
            cp_wait<1>();
        } else cp_wait<0>();
        __syncthreads();

        const __half* vb = hkv + (c & 1) * (CK * KLDh);
#pragma unroll
        for (int kk = 0; kk < CK; kk += 16) {
            wmma::fragment<wmma::matrix_a, 16, 16, 16, __half, wmma::row_major> af;
            wmma::fragment<wmma::matrix_b, 16, 16, 16, __half, wmma::row_major> bf;
            wmma::load_matrix_sync(af, hp + (size_t)(tm * 16) * (SLDa * 2) + c * 128 + kk,
                                   SLDa * 2);
            wmma::load_matrix_sync(bf, vb + kk * KLDh + tn * 16, KLDh);
            wmma::mma_sync(accO, af, bf, accO);
        }
        __syncthreads();
    }

    // stage 32x64 fp32 result, convert to half, coalesced store
    float* St2 = f + OS_S;          // [32][68]
    wmma::store_matrix_sync(St2 + (tm * 16) * 68 + tn * 16, accO, 68, wmma::mem_row_major);
    __syncthreads();
    for (int idx = tid; idx < QB * 64; idx += 256) {
        int r = idx >> 6, c = idx & 63;
        out[(size_t)(bv * Tc + q0 + r) * Dc + h * DHc + c] = __float2half(St2[r * 68 + c]);
    }
}

// ---------------- launch ----------------
extern "C" void kernel_launch(void* const* d_in, const int* in_sizes, int n_in,
                              void* d_out, int out_size)
{
    const float* x  = (const float*)d_in[0];
    const int* mask = (const int*)d_in[1];          // bool -> int32 in harness
    const float* Wq = (const float*)d_in[2];
    const float* bq = (const float*)d_in[3];
    const float* Wk = (const float*)d_in[4];
    const float* bk = (const float*)d_in[5];
    const float* Wv = (const float*)d_in[6];
    const float* bvb = (const float*)d_in[7];
    const float* Wo = (const float*)d_in[8];
    const float* bo = (const float*)d_in[9];
    const float* W1 = (const float*)d_in[10];
    const float* b1 = (const float*)d_in[11];
    const float* W2 = (const float*)d_in[12];
    const float* b2 = (const float*)d_in[13];
    const float* g1 = (const float*)d_in[14];
    const float* be1 = (const float*)d_in[15];
    const float* g2 = (const float*)d_in[16];
    const float* be2 = (const float*)d_in[17];
    float* out = (float*)d_out;

    __half *xnh, *qh, *kh, *vh, *ath, *h2h, *ffh, *wqkv, *who, *wh1, *wh2;
    float *xr, *bqkv;
    cudaGetSymbolAddress((void**)&xnh,  g_xnh);
    cudaGetSymbolAddress((void**)&qh,   g_qh);
    cudaGetSymbolAddress((void**)&kh,   g_kh);
    cudaGetSymbolAddress((void**)&vh,   g_vh);
    cudaGetSymbolAddress((void**)&ath,  g_ath);
    cudaGetSymbolAddress((void**)&h2h,  g_h2h);
    cudaGetSymbolAddress((void**)&ffh,  g_ffh);
    cudaGetSymbolAddress((void**)&xr,   g_xr);
    cudaGetSymbolAddress((void**)&wqkv, g_wqkv);
    cudaGetSymbolAddress((void**)&bqkv, g_bqkv);
    cudaGetSymbolAddress((void**)&who,  g_who);
    cudaGetSymbolAddress((void**)&wh1,  g_wh1);
    cudaGetSymbolAddress((void**)&wh2,  g_wh2);

    cudaFuncSetAttribute(gemm_h<0>, cudaFuncAttributeMaxDynamicSharedMemorySize, (int)SMH);
    cudaFuncSetAttribute(gemm_h<1>, cudaFuncAttributeMaxDynamicSharedMemorySize, (int)SMH);
    cudaFuncSetAttribute(gemm_h<2>, cudaFuncAttributeMaxDynamicSharedMemorySize, (int)SMH);
    cudaFuncSetAttribute(gemm_h<3>, cudaFuncAttributeMaxDynamicSharedMemorySize, (int)SMH);
    cudaFuncSetAttribute(attn_kernel, cudaFuncAttributeMaxDynamicSharedMemorySize, (int)SMA);

    // 0. weights fp32 -> fp16 (QKV concatenated into [512][1536])
    wconv_off<<<Dc * Dc / 4 / 256, 256>>>(Wq, wqkv, 0);
    wconv_off<<<Dc * Dc / 4 / 256, 256>>>(Wk, wqkv, Dc);
    wconv_off<<<Dc * Dc / 4 / 256, 256>>>(Wv, wqkv, 2 * Dc);
    bcat<<<2, 256>>>(bq, bk, bvb, bqkv);
    wconv<<<Dc * Dc / 4 / 256, 256>>>(Wo, who, Dc * Dc / 4);
    wconv<<<Dc * DFFc / 4 / 256, 256>>>(W1, wh1, Dc * DFFc / 4);
    wconv<<<DFFc * Dc / 4 / 256, 256>>>(W2, wh2, DFFc * Dc / 4);

    dim3 gqkv(3 * Dc / BN, MTOK / BM);   // (12, 768)
    dim3 g512(Dc / BN, MTOK / BM);       // (4, 768)
    dim3 gff(DFFc / BN, MTOK / BM);      // (16, 768)

    // 1. LN1 (gather-transpose from x) -> half
    ln_kernel<<<MTOK / 8, 256>>>(x, g1, be1, xnh, 1);
    // 2. merged QKV projection -> head-major half
    gemm_h<0><<<gqkv, 256, SMH>>>(xnh, wqkv, MTOK, 3 * Dc, Dc, bqkv, nullptr,
                                  nullptr, qh, kh, vh);
    // 3. Attention -> half
    attn_kernel<<<dim3(Tc / QB, Hc, BV), 256, SMA>>>(qh, kh, vh, mask, ath);
    // 4. O-projection + residual (x gathered) -> xr fp32
    gemm_h<1><<<g512, 256, SMH>>>(ath, who, MTOK, Dc, Dc, bo, x, xr, nullptr,
                                  nullptr, nullptr);
    // 5. LN2 -> half
    ln_kernel<<<MTOK / 8, 256>>>(xr, g2, be2, h2h, 0);
    // 6. FFN1 + bias + exact gelu -> half
    gemm_h<2><<<gff, 256, SMH>>>(h2h, wh1, MTOK, DFFc, Dc, b1, nullptr,
                                 nullptr, ffh, nullptr, nullptr);
    // 7. FFN2 + bias + residual + scatter-transpose -> fp32 d_out
    gemm_h<3><<<g512, 256, SMH>>>(ffh, wh2, MTOK, Dc, DFFc, b2, xr, out,
                                  nullptr, nullptr, nullptr);
}